// round 1
// baseline (speedup 1.0000x reference)
#include <cuda_runtime.h>

#define BATCH 32
#define CH    256
#define HW    1024
#define GROUPS 8
#define CPG   32           // channels per group
#define EPSV  1e-5f
#define SCALE 0.0625f      // 1/sqrt(256)

// ---------------- scratch (device globals; no allocation allowed) ----------
__device__ float g_xn  [(size_t)BATCH * CH * HW];        //  33.5 MB
__device__ float g_qkv [(size_t)BATCH * 3 * CH * HW];    // 100.7 MB
__device__ float g_attn[(size_t)BATCH * HW * HW];        // 134.2 MB
__device__ float g_ao  [(size_t)BATCH * CH * HW];        //  33.5 MB

// ---------------- GroupNorm -------------------------------------------------
// grid = BATCH*GROUPS blocks of 256 threads. Each group = contiguous 32768 floats.
__global__ void gn_kernel(const float* __restrict__ x,
                          const float* __restrict__ wt,
                          const float* __restrict__ bs)
{
    const int bg = blockIdx.x;                  // 0..255
    const int g  = bg & (GROUPS - 1);
    const size_t base = (size_t)bg * (CPG * HW);
    const float4* x4 = (const float4*)(x + base);
    float4* y4 = (float4*)(g_xn + base);
    const int t = threadIdx.x;

    float s = 0.f, s2 = 0.f;
    #pragma unroll 4
    for (int i = t; i < CPG * HW / 4; i += 256) {
        float4 v = x4[i];
        s  += v.x + v.y + v.z + v.w;
        s2 += v.x*v.x + v.y*v.y + v.z*v.z + v.w*v.w;
    }
    __shared__ float rs[256], rq[256];
    rs[t] = s; rq[t] = s2;
    __syncthreads();
    for (int o = 128; o > 0; o >>= 1) {
        if (t < o) { rs[t] += rs[t+o]; rq[t] += rq[t+o]; }
        __syncthreads();
    }
    __shared__ float s_mean, s_rstd;
    if (t == 0) {
        float m = rs[0] * (1.0f / (CPG * HW));
        float v = rq[0] * (1.0f / (CPG * HW)) - m * m;
        s_mean = m;
        s_rstd = rsqrtf(v + EPSV);
    }
    __syncthreads();
    const float m = s_mean, r = s_rstd;
    for (int i = t; i < CPG * HW / 4; i += 256) {
        int c = g * CPG + (i >> 8);             // (i*4)/1024
        float w  = wt[c] * r;
        float bb = bs[c] - m * w;
        float4 v = x4[i];
        float4 o;
        o.x = v.x * w + bb; o.y = v.y * w + bb;
        o.z = v.z * w + bb; o.w = v.w * w + bb;
        y4[i] = o;
    }
}

// ---------------- GEMM qkv:  C[768,1024] = W[768,256] * Xn[256,1024] + bias -
// 64x64 tiles, BK=16, 256 threads, 4x4 per thread.
__global__ void gemm_qkv(const float* __restrict__ W,
                         const float* __restrict__ bias)
{
    const int bz = blockIdx.z;
    const float* Bp = g_xn  + (size_t)bz * CH * HW;
    float*       Cp = g_qkv + (size_t)bz * 3 * CH * HW;
    const int bm = blockIdx.y * 64, bn = blockIdx.x * 64;
    const int t = threadIdx.x, tx = t & 15, ty = t >> 4;

    __shared__ float As[16][66];
    __shared__ float Bs[16][66];
    float acc[4][4] = {};

    for (int k0 = 0; k0 < CH; k0 += 16) {
        { // A tile 64x16 -> As[k][m]
            int r = t >> 2, kq = (t & 3) << 2;
            float4 v = *(const float4*)&W[(size_t)(bm + r) * CH + k0 + kq];
            As[kq+0][r] = v.x; As[kq+1][r] = v.y; As[kq+2][r] = v.z; As[kq+3][r] = v.w;
        }
        { // B tile 16x64 -> Bs[k][n]
            int kr = t >> 4, nq = (t & 15) << 2;
            float4 v = *(const float4*)&Bp[(size_t)(k0 + kr) * HW + bn + nq];
            Bs[kr][nq+0] = v.x; Bs[kr][nq+1] = v.y; Bs[kr][nq+2] = v.z; Bs[kr][nq+3] = v.w;
        }
        __syncthreads();
        #pragma unroll
        for (int kk = 0; kk < 16; kk++) {
            float a[4], b[4];
            #pragma unroll
            for (int i = 0; i < 4; i++) a[i] = As[kk][ty*4 + i];
            #pragma unroll
            for (int j = 0; j < 4; j++) b[j] = Bs[kk][tx*4 + j];
            #pragma unroll
            for (int i = 0; i < 4; i++)
                #pragma unroll
                for (int j = 0; j < 4; j++)
                    acc[i][j] += a[i] * b[j];
        }
        __syncthreads();
    }
    #pragma unroll
    for (int i = 0; i < 4; i++) {
        int row = bm + ty*4 + i;
        float bb = bias[row];
        #pragma unroll
        for (int j = 0; j < 4; j++) {
            int col = bn + tx*4 + j;
            Cp[(size_t)row * HW + col] = acc[i][j] + bb;
        }
    }
}

// ---------------- GEMM S = scale * Q^T K  (tn form) -------------------------
// Q,K stored [256][1024] (channel-major). S[s,t], M=N=1024, K=256.
__global__ void gemm_qk()
{
    const int bz = blockIdx.z;
    const float* Q  = g_qkv + (size_t)bz * 3 * CH * HW;
    const float* Km = Q + (size_t)CH * HW;
    float*       S  = g_attn + (size_t)bz * HW * HW;
    const int bm = blockIdx.y * 64, bn = blockIdx.x * 64;
    const int t = threadIdx.x, tx = t & 15, ty = t >> 4;

    __shared__ float As[16][66];
    __shared__ float Bs[16][66];
    float acc[4][4] = {};

    for (int k0 = 0; k0 < CH; k0 += 16) {
        {
            int kr = t >> 4, mq = (t & 15) << 2;
            float4 v = *(const float4*)&Q[(size_t)(k0 + kr) * HW + bm + mq];
            As[kr][mq+0] = v.x; As[kr][mq+1] = v.y; As[kr][mq+2] = v.z; As[kr][mq+3] = v.w;
            float4 w = *(const float4*)&Km[(size_t)(k0 + kr) * HW + bn + mq];
            Bs[kr][mq+0] = w.x; Bs[kr][mq+1] = w.y; Bs[kr][mq+2] = w.z; Bs[kr][mq+3] = w.w;
        }
        __syncthreads();
        #pragma unroll
        for (int kk = 0; kk < 16; kk++) {
            float a[4], b[4];
            #pragma unroll
            for (int i = 0; i < 4; i++) a[i] = As[kk][ty*4 + i];
            #pragma unroll
            for (int j = 0; j < 4; j++) b[j] = Bs[kk][tx*4 + j];
            #pragma unroll
            for (int i = 0; i < 4; i++)
                #pragma unroll
                for (int j = 0; j < 4; j++)
                    acc[i][j] += a[i] * b[j];
        }
        __syncthreads();
    }
    #pragma unroll
    for (int i = 0; i < 4; i++) {
        int row = bm + ty*4 + i;
        #pragma unroll
        for (int j = 0; j < 4; j++) {
            int col = bn + tx*4 + j;
            S[(size_t)row * HW + col] = acc[i][j] * SCALE;
        }
    }
}

// ---------------- softmax over last dim (1024) ------------------------------
// one block (256 threads) per row; each thread owns 4 contiguous floats.
__global__ void softmax_kernel()
{
    float* row = g_attn + (size_t)blockIdx.x * HW;
    const int t = threadIdx.x;
    float4 v = ((float4*)row)[t];

    float m = fmaxf(fmaxf(v.x, v.y), fmaxf(v.z, v.w));
    #pragma unroll
    for (int o = 16; o > 0; o >>= 1) m = fmaxf(m, __shfl_xor_sync(0xffffffffu, m, o));
    __shared__ float red[8];
    if ((t & 31) == 0) red[t >> 5] = m;
    __syncthreads();
    float mm = red[0];
    #pragma unroll
    for (int i = 1; i < 8; i++) mm = fmaxf(mm, red[i]);
    __syncthreads();

    float e0 = __expf(v.x - mm), e1 = __expf(v.y - mm);
    float e2 = __expf(v.z - mm), e3 = __expf(v.w - mm);
    float s = e0 + e1 + e2 + e3;
    #pragma unroll
    for (int o = 16; o > 0; o >>= 1) s += __shfl_xor_sync(0xffffffffu, s, o);
    if ((t & 31) == 0) red[t >> 5] = s;
    __syncthreads();
    float tot = 0.f;
    #pragma unroll
    for (int i = 0; i < 8; i++) tot += red[i];
    float inv = 1.0f / tot;

    float4 o; o.x = e0 * inv; o.y = e1 * inv; o.z = e2 * inv; o.w = e3 * inv;
    ((float4*)row)[t] = o;
}

// ---------------- GEMM O = V * P^T  (nt form) -------------------------------
// V[256][1024] (k = t contiguous), P[1024][1024] accessed [s][t]. M=256,N=1024,K=1024.
__global__ void gemm_av()
{
    const int bz = blockIdx.z;
    const float* V = g_qkv + (size_t)bz * 3 * CH * HW + (size_t)2 * CH * HW;
    const float* P = g_attn + (size_t)bz * HW * HW;
    float*       O = g_ao   + (size_t)bz * CH * HW;
    const int bm = blockIdx.y * 64, bn = blockIdx.x * 64;
    const int t = threadIdx.x, tx = t & 15, ty = t >> 4;

    __shared__ float As[16][66];
    __shared__ float Bs[16][66];
    float acc[4][4] = {};

    for (int k0 = 0; k0 < HW; k0 += 16) {
        {
            int r = t >> 2, kq = (t & 3) << 2;
            float4 v = *(const float4*)&V[(size_t)(bm + r) * HW + k0 + kq];
            As[kq+0][r] = v.x; As[kq+1][r] = v.y; As[kq+2][r] = v.z; As[kq+3][r] = v.w;
            float4 w = *(const float4*)&P[(size_t)(bn + r) * HW + k0 + kq];
            Bs[kq+0][r] = w.x; Bs[kq+1][r] = w.y; Bs[kq+2][r] = w.z; Bs[kq+3][r] = w.w;
        }
        __syncthreads();
        #pragma unroll
        for (int kk = 0; kk < 16; kk++) {
            float a[4], b[4];
            #pragma unroll
            for (int i = 0; i < 4; i++) a[i] = As[kk][ty*4 + i];
            #pragma unroll
            for (int j = 0; j < 4; j++) b[j] = Bs[kk][tx*4 + j];
            #pragma unroll
            for (int i = 0; i < 4; i++)
                #pragma unroll
                for (int j = 0; j < 4; j++)
                    acc[i][j] += a[i] * b[j];
        }
        __syncthreads();
    }
    #pragma unroll
    for (int i = 0; i < 4; i++) {
        int row = bm + ty*4 + i;
        #pragma unroll
        for (int j = 0; j < 4; j++) {
            int col = bn + tx*4 + j;
            O[(size_t)row * HW + col] = acc[i][j];
        }
    }
}

// ---------------- out proj + bias + residual --------------------------------
// out[256,1024] = Wout[256,256] * O[256,1024] + bout + x
__global__ void gemm_out(const float* __restrict__ W,
                         const float* __restrict__ bias,
                         const float* __restrict__ x,
                         float* __restrict__ out)
{
    const int bz = blockIdx.z;
    const float* Bp = g_ao + (size_t)bz * CH * HW;
    const float* Rp = x    + (size_t)bz * CH * HW;
    float*       Cp = out  + (size_t)bz * CH * HW;
    const int bm = blockIdx.y * 64, bn = blockIdx.x * 64;
    const int t = threadIdx.x, tx = t & 15, ty = t >> 4;

    __shared__ float As[16][66];
    __shared__ float Bs[16][66];
    float acc[4][4] = {};

    for (int k0 = 0; k0 < CH; k0 += 16) {
        {
            int r = t >> 2, kq = (t & 3) << 2;
            float4 v = *(const float4*)&W[(size_t)(bm + r) * CH + k0 + kq];
            As[kq+0][r] = v.x; As[kq+1][r] = v.y; As[kq+2][r] = v.z; As[kq+3][r] = v.w;
        }
        {
            int kr = t >> 4, nq = (t & 15) << 2;
            float4 v = *(const float4*)&Bp[(size_t)(k0 + kr) * HW + bn + nq];
            Bs[kr][nq+0] = v.x; Bs[kr][nq+1] = v.y; Bs[kr][nq+2] = v.z; Bs[kr][nq+3] = v.w;
        }
        __syncthreads();
        #pragma unroll
        for (int kk = 0; kk < 16; kk++) {
            float a[4], b[4];
            #pragma unroll
            for (int i = 0; i < 4; i++) a[i] = As[kk][ty*4 + i];
            #pragma unroll
            for (int j = 0; j < 4; j++) b[j] = Bs[kk][tx*4 + j];
            #pragma unroll
            for (int i = 0; i < 4; i++)
                #pragma unroll
                for (int j = 0; j < 4; j++)
                    acc[i][j] += a[i] * b[j];
        }
        __syncthreads();
    }
    #pragma unroll
    for (int i = 0; i < 4; i++) {
        int row = bm + ty*4 + i;
        float bb = bias[row];
        #pragma unroll
        for (int j = 0; j < 4; j++) {
            int col = bn + tx*4 + j;
            size_t idx = (size_t)row * HW + col;
            Cp[idx] = acc[i][j] + bb + Rp[idx];
        }
    }
}

// ---------------- launch ------------------------------------------------------
extern "C" void kernel_launch(void* const* d_in, const int* in_sizes, int n_in,
                              void* d_out, int out_size)
{
    const float* x    = (const float*)d_in[0];
    const float* gnw  = (const float*)d_in[1];
    const float* gnb  = (const float*)d_in[2];
    const float* wqkv = (const float*)d_in[3];
    const float* bqkv = (const float*)d_in[4];
    const float* wout = (const float*)d_in[5];
    const float* bout = (const float*)d_in[6];
    float* out = (float*)d_out;

    gn_kernel<<<BATCH * GROUPS, 256>>>(x, gnw, gnb);
    gemm_qkv<<<dim3(HW/64, (3*CH)/64, BATCH), 256>>>(wqkv, bqkv);
    gemm_qk <<<dim3(HW/64, HW/64, BATCH), 256>>>();
    softmax_kernel<<<BATCH * HW, 256>>>();
    gemm_av <<<dim3(HW/64, CH/64, BATCH), 256>>>();
    gemm_out<<<dim3(HW/64, CH/64, BATCH), 256>>>(wout, bout, x, out);
}

// round 3
// speedup vs baseline: 2.6052x; 2.6052x over previous
#include <cuda_runtime.h>
#include <cuda_bf16.h>
#include <cstdint>

#define BATCH 32
#define CH    256
#define HW    1024
#define EPSV  1e-5f
#define SCALE 0.0625f

// ---------------- scratch (device globals; no allocation allowed) ----------
__device__ float g_xnt [(size_t)BATCH * HW * CH];   // x_norm^T [b][s][c]
__device__ float g_q   [(size_t)BATCH * HW * CH];   // [b][s][c]
__device__ float g_k   [(size_t)BATCH * HW * CH];   // [b][s][c]
__device__ float g_vt  [(size_t)BATCH * HW * CH];   // [b][t][c]
__device__ float g_v   [(size_t)BATCH * CH * HW];   // [b][c][t]
__device__ float g_attn[(size_t)BATCH * HW * HW];   // [b][s][t]
__device__ float g_ao  [(size_t)BATCH * HW * CH];   // [b][s][c]

// ---------------- helpers ----------------------------------------------------
__device__ __forceinline__ uint32_t smem_u32(const void* p) {
    uint32_t a;
    asm("{ .reg .u64 t; cvta.to.shared.u64 t, %1; cvt.u32.u64 %0, t; }" : "=r"(a) : "l"(p));
    return a;
}

__device__ __forceinline__ void ldsm4(uint32_t* r, uint32_t addr) {
    asm volatile("ldmatrix.sync.aligned.m8n8.x4.shared.b16 {%0,%1,%2,%3}, [%4];"
        : "=r"(r[0]), "=r"(r[1]), "=r"(r[2]), "=r"(r[3]) : "r"(addr));
}

__device__ __forceinline__ void mma16816(float* c, const uint32_t* a, uint32_t b0, uint32_t b1) {
    asm volatile("mma.sync.aligned.m16n8k16.row.col.f32.bf16.bf16.f32 "
        "{%0,%1,%2,%3}, {%4,%5,%6,%7}, {%8,%9}, {%0,%1,%2,%3};"
        : "+f"(c[0]), "+f"(c[1]), "+f"(c[2]), "+f"(c[3])
        : "r"(a[0]), "r"(a[1]), "r"(a[2]), "r"(a[3]), "r"(b0), "r"(b1));
}

// split fp32 -> bf16 hi/lo, store 4 elements (8B each) into padded smem
__device__ __forceinline__ void cvt_store(float4 v, __nv_bfloat16* hi, __nv_bfloat16* lo, int off) {
    __nv_bfloat162 h01 = __floats2bfloat162_rn(v.x, v.y);
    __nv_bfloat162 h23 = __floats2bfloat162_rn(v.z, v.w);
    float lx = v.x - __bfloat162float(h01.x);
    float ly = v.y - __bfloat162float(h01.y);
    float lz = v.z - __bfloat162float(h23.x);
    float lw = v.w - __bfloat162float(h23.y);
    __nv_bfloat162 l01 = __floats2bfloat162_rn(lx, ly);
    __nv_bfloat162 l23 = __floats2bfloat162_rn(lz, lw);
    uint2 hv, lv;
    hv.x = *(uint32_t*)&h01; hv.y = *(uint32_t*)&h23;
    lv.x = *(uint32_t*)&l01; lv.y = *(uint32_t*)&l23;
    *(uint2*)(hi + off) = hv;
    *(uint2*)(lo + off) = lv;
}

__device__ __forceinline__ void st2(float* p, float x, float y) {
    float2 v; v.x = x; v.y = y; *(float2*)p = v;
}

// ---------------- unified HMMA GEMM ------------------------------------------
// D[m][n] = sum_k A[m][k]*B[n][k], K-major fp32 operands split into bf16 hi/lo.
// MODE 0: A=xnt[s][c],  B=w_qkv[o][c], K=256  -> q/k/vt [s|t][c] + bias
// MODE 1: A=q[s][c],    B=k[t][c],    K=256  -> attn[s][t] * SCALE
// MODE 2: A=attn[s][t], B=v[c][t],    K=1024 -> ao[s][c]
// MODE 3: A=w_out[o][c],B=ao[s][c],   K=256  -> out[o][s] + bias + resid
#define LDS 40   // padded bf16 row stride (80B): conflict-free ldmatrix
template <int MODE>
__global__ void __launch_bounds__(512, 1) mma_gemm(
    const float* __restrict__ W, const float* __restrict__ bias,
    const float* __restrict__ resid, float* __restrict__ Cout)
{
    constexpr int KTOT = (MODE == 2) ? 1024 : 256;
    constexpr int NCH = KTOT / 32;
    __shared__ __nv_bfloat16 sAh[128 * LDS], sAl[128 * LDS];
    __shared__ __nv_bfloat16 sBh[128 * LDS], sBl[128 * LDS];

    const int tid = threadIdx.x;
    const int lane = tid & 31, wid = tid >> 5;
    const int bz = blockIdx.z;
    const int bm = blockIdx.y * 128, bn = blockIdx.x * 128;

    const float *A, *B;
    if (MODE == 0) { A = g_xnt + (size_t)bz * HW * CH; B = W; }
    if (MODE == 1) { A = g_q + (size_t)bz * HW * CH;   B = g_k + (size_t)bz * HW * CH; }
    if (MODE == 2) { A = g_attn + (size_t)bz * HW * HW; B = g_v + (size_t)bz * CH * HW; }
    if (MODE == 3) { A = W; B = g_ao + (size_t)bz * HW * CH; }

    // staging: thread covers rows r0 and r0+64, 4 floats at col c0
    const int r0 = tid >> 3, c0 = (tid & 7) << 2;
    const float* Ar0 = A + (size_t)(bm + r0) * KTOT + c0;
    const float* Ar1 = Ar0 + (size_t)64 * KTOT;
    const float* Br0 = B + (size_t)(bn + r0) * KTOT + c0;
    const float* Br1 = Br0 + (size_t)64 * KTOT;
    const int so0 = r0 * LDS + c0, so1 = (r0 + 64) * LDS + c0;

    const int wm = (wid >> 2) * 32, wn = (wid & 3) * 32;

    // ldmatrix base addresses
    const uint32_t uAh = smem_u32(sAh), uAl = smem_u32(sAl);
    const uint32_t uBh = smem_u32(sBh), uBl = smem_u32(sBl);
    const int rowA = wm + (lane & 15);
    const int kOffA = (lane >> 4) << 3;
    const int rowB = wn + (lane & 7) + ((lane >> 4) << 3);
    const int kOffB = ((lane >> 3) & 1) << 3;
    uint32_t aHb[2], aLb[2], bHb[2], bLb[2];
#pragma unroll
    for (int mt = 0; mt < 2; mt++) {
        aHb[mt] = uAh + (uint32_t)(((rowA + mt * 16) * LDS + kOffA) * 2);
        aLb[mt] = uAl + (uint32_t)(((rowA + mt * 16) * LDS + kOffA) * 2);
    }
#pragma unroll
    for (int p = 0; p < 2; p++) {
        bHb[p] = uBh + (uint32_t)(((rowB + p * 16) * LDS + kOffB) * 2);
        bLb[p] = uBl + (uint32_t)(((rowB + p * 16) * LDS + kOffB) * 2);
    }

    float acc[2][4][4] = {};
    float4 av0 = *(const float4*)Ar0;
    float4 av1 = *(const float4*)Ar1;
    float4 bv0 = *(const float4*)Br0;
    float4 bv1 = *(const float4*)Br1;

    for (int ch = 0; ch < NCH; ch++) {
        __syncthreads();
        cvt_store(av0, sAh, sAl, so0);
        cvt_store(av1, sAh, sAl, so1);
        cvt_store(bv0, sBh, sBl, so0);
        cvt_store(bv1, sBh, sBl, so1);
        __syncthreads();
        if (ch + 1 < NCH) {
            const int k = (ch + 1) * 32;
            av0 = *(const float4*)(Ar0 + k);
            av1 = *(const float4*)(Ar1 + k);
            bv0 = *(const float4*)(Br0 + k);
            bv1 = *(const float4*)(Br1 + k);
        }
#pragma unroll
        for (int ks = 0; ks < 2; ks++) {
            uint32_t ah[2][4], al[2][4], bh[2][4], bl[2][4];
#pragma unroll
            for (int mt = 0; mt < 2; mt++) {
                ldsm4(ah[mt], aHb[mt] + ks * 32);
                ldsm4(al[mt], aLb[mt] + ks * 32);
            }
#pragma unroll
            for (int p = 0; p < 2; p++) {
                ldsm4(bh[p], bHb[p] + ks * 32);
                ldsm4(bl[p], bLb[p] + ks * 32);
            }
#pragma unroll
            for (int mt = 0; mt < 2; mt++)
#pragma unroll
                for (int p = 0; p < 2; p++)
#pragma unroll
                    for (int h = 0; h < 2; h++) {
                        float* c = acc[mt][p * 2 + h];
                        mma16816(c, ah[mt], bh[p][h * 2], bh[p][h * 2 + 1]);
                        mma16816(c, ah[mt], bl[p][h * 2], bl[p][h * 2 + 1]);
                        mma16816(c, al[mt], bh[p][h * 2], bh[p][h * 2 + 1]);
                    }
        }
    }

    // ---------------- epilogue (n-contiguous float2 stores) -----------------
    const int gid = lane >> 2, qid = (lane & 3) * 2;

    if (MODE == 0) {
        const int bx = blockIdx.x;
        const int third = bx >> 1;
        const int cb = (bx & 1) * 128;
        float* dst = (third == 0 ? g_q : third == 1 ? g_k : g_vt) + (size_t)bz * HW * CH;
#pragma unroll
        for (int mt = 0; mt < 2; mt++) {
            const int s = bm + wm + mt * 16 + gid;
#pragma unroll
            for (int nt = 0; nt < 4; nt++) {
                const int cl = wn + nt * 8 + qid;
                const float b0v = bias[bx * 128 + cl];
                const float b1v = bias[bx * 128 + cl + 1];
                float* a = acc[mt][nt];
                st2(&dst[(size_t)s * CH + cb + cl], a[0] + b0v, a[1] + b1v);
                st2(&dst[(size_t)(s + 8) * CH + cb + cl], a[2] + b0v, a[3] + b1v);
            }
        }
    }
    if (MODE == 1) {
        float* dst = g_attn + (size_t)bz * HW * HW;
#pragma unroll
        for (int mt = 0; mt < 2; mt++) {
            const int s = bm + wm + mt * 16 + gid;
#pragma unroll
            for (int nt = 0; nt < 4; nt++) {
                const int t = bn + wn + nt * 8 + qid;
                float* a = acc[mt][nt];
                st2(&dst[(size_t)s * HW + t], a[0] * SCALE, a[1] * SCALE);
                st2(&dst[(size_t)(s + 8) * HW + t], a[2] * SCALE, a[3] * SCALE);
            }
        }
    }
    if (MODE == 2) {
        float* dst = g_ao + (size_t)bz * HW * CH;
#pragma unroll
        for (int mt = 0; mt < 2; mt++) {
            const int s = bm + wm + mt * 16 + gid;
#pragma unroll
            for (int nt = 0; nt < 4; nt++) {
                const int c = bn + wn + nt * 8 + qid;
                float* a = acc[mt][nt];
                st2(&dst[(size_t)s * CH + c], a[0], a[1]);
                st2(&dst[(size_t)(s + 8) * CH + c], a[2], a[3]);
            }
        }
    }
    if (MODE == 3) {
#pragma unroll
        for (int mt = 0; mt < 2; mt++) {
            const int o = bm + wm + mt * 16 + gid;
            const float bo0 = bias[o], bo8 = bias[o + 8];
#pragma unroll
            for (int nt = 0; nt < 4; nt++) {
                const int s = bn + wn + nt * 8 + qid;
                float* a = acc[mt][nt];
                size_t i0 = ((size_t)bz * CH + o) * HW + s;
                size_t i1 = ((size_t)bz * CH + o + 8) * HW + s;
                float2 rv0 = *(const float2*)&resid[i0];
                float2 rv1 = *(const float2*)&resid[i1];
                st2(&Cout[i0], a[0] + bo0 + rv0.x, a[1] + bo0 + rv0.y);
                st2(&Cout[i1], a[2] + bo8 + rv1.x, a[3] + bo8 + rv1.y);
            }
        }
    }
}

// ---------------- GroupNorm (writes x_norm^T [b][s][c]) ----------------------
__global__ void gn_kernel(const float* __restrict__ x,
                          const float* __restrict__ wt,
                          const float* __restrict__ bs)
{
    const int bg = blockIdx.x;              // b*8+g
    const int b = bg >> 3, g = bg & 7;
    const size_t base = (size_t)bg * (32 * HW);
    const int t = threadIdx.x;
    const float4* x4 = (const float4*)(x + base);

    float s = 0.f, s2 = 0.f;
#pragma unroll 4
    for (int i = t; i < 32 * HW / 4; i += 256) {
        float4 v = x4[i];
        s += v.x + v.y + v.z + v.w;
        s2 += v.x * v.x + v.y * v.y + v.z * v.z + v.w * v.w;
    }
    __shared__ float rs[256], rq[256];
    rs[t] = s; rq[t] = s2;
    __syncthreads();
    for (int o = 128; o > 0; o >>= 1) {
        if (t < o) { rs[t] += rs[t + o]; rq[t] += rq[t + o]; }
        __syncthreads();
    }
    __shared__ float s_m, s_r;
    if (t == 0) {
        float m = rs[0] * (1.0f / (32.f * HW));
        float v = rq[0] * (1.0f / (32.f * HW)) - m * m;
        s_m = m; s_r = rsqrtf(v + EPSV);
    }
    __syncthreads();
    __shared__ float cw[32], cb[32];
    if (t < 32) {
        float w = wt[g * 32 + t] * s_r;
        cw[t] = w;
        cb[t] = bs[g * 32 + t] - s_m * w;
    }
    __syncthreads();

    __shared__ float sm[32][33];
    const int row = t >> 5, col = t & 31;
    for (int s0 = 0; s0 < HW; s0 += 32) {
#pragma unroll
        for (int cr = 0; cr < 32; cr += 8) {
            int c = cr + row;
            sm[c][col] = x[base + (size_t)c * HW + s0 + col] * cw[c] + cb[c];
        }
        __syncthreads();
#pragma unroll
        for (int sr = 0; sr < 32; sr += 8) {
            int sl = sr + row;
            g_xnt[((size_t)b * HW + s0 + sl) * CH + g * 32 + col] = sm[col][sl];
        }
        __syncthreads();
    }
}

// ---------------- v transpose: vt[t][c] -> v[c][t] ---------------------------
__global__ void transpose_v()
{
    __shared__ float tile[32][33];
    const int b = blockIdx.z;
    const int t0 = blockIdx.x * 32;
    const int c0 = blockIdx.y * 32;
    const int x = threadIdx.x, y = threadIdx.y;
    const float* src = g_vt + (size_t)b * HW * CH;
    float* dst = g_v + (size_t)b * CH * HW;
#pragma unroll
    for (int j = 0; j < 32; j += 8)
        tile[y + j][x] = src[(size_t)(t0 + y + j) * CH + c0 + x];
    __syncthreads();
#pragma unroll
    for (int j = 0; j < 32; j += 8)
        dst[(size_t)(c0 + y + j) * HW + t0 + x] = tile[x][y + j];
}

// ---------------- softmax over last dim (1024) --------------------------------
__global__ void softmax_kernel()
{
    float* row = g_attn + (size_t)blockIdx.x * HW;
    const int t = threadIdx.x;
    float4 v = ((float4*)row)[t];

    float m = fmaxf(fmaxf(v.x, v.y), fmaxf(v.z, v.w));
#pragma unroll
    for (int o = 16; o > 0; o >>= 1) m = fmaxf(m, __shfl_xor_sync(0xffffffffu, m, o));
    __shared__ float red[8];
    if ((t & 31) == 0) red[t >> 5] = m;
    __syncthreads();
    float mm = red[0];
#pragma unroll
    for (int i = 1; i < 8; i++) mm = fmaxf(mm, red[i]);
    __syncthreads();

    float e0 = __expf(v.x - mm), e1 = __expf(v.y - mm);
    float e2 = __expf(v.z - mm), e3 = __expf(v.w - mm);
    float s = e0 + e1 + e2 + e3;
#pragma unroll
    for (int o = 16; o > 0; o >>= 1) s += __shfl_xor_sync(0xffffffffu, s, o);
    if ((t & 31) == 0) red[t >> 5] = s;
    __syncthreads();
    float tot = 0.f;
#pragma unroll
    for (int i = 0; i < 8; i++) tot += red[i];
    float inv = 1.0f / tot;

    float4 o4; o4.x = e0 * inv; o4.y = e1 * inv; o4.z = e2 * inv; o4.w = e3 * inv;
    ((float4*)row)[t] = o4;
}

// ---------------- launch -------------------------------------------------------
extern "C" void kernel_launch(void* const* d_in, const int* in_sizes, int n_in,
                              void* d_out, int out_size)
{
    const float* x    = (const float*)d_in[0];
    const float* gnw  = (const float*)d_in[1];
    const float* gnb  = (const float*)d_in[2];
    const float* wqkv = (const float*)d_in[3];
    const float* bqkv = (const float*)d_in[4];
    const float* wout = (const float*)d_in[5];
    const float* bout = (const float*)d_in[6];
    float* out = (float*)d_out;

    gn_kernel<<<BATCH * 8, 256>>>(x, gnw, gnb);
    mma_gemm<0><<<dim3(6, 8, BATCH), 512>>>(wqkv, bqkv, nullptr, nullptr);
    transpose_v<<<dim3(HW / 32, CH / 32, BATCH), dim3(32, 8)>>>();
    mma_gemm<1><<<dim3(8, 8, BATCH), 512>>>(nullptr, nullptr, nullptr, nullptr);
    softmax_kernel<<<BATCH * HW, 256>>>();
    mma_gemm<2><<<dim3(2, 8, BATCH), 512>>>(nullptr, nullptr, nullptr, nullptr);
    mma_gemm<3><<<dim3(8, 2, BATCH), 512>>>(wout, bout, x, out);
}

// round 4
// speedup vs baseline: 2.8695x; 1.1015x over previous
#include <cuda_runtime.h>
#include <cuda_bf16.h>
#include <cstdint>

#define BATCH 32
#define CH    256
#define HW    1024
#define EPSV  1e-5f
#define SCALE 0.0625f

// ---------------- scratch (device globals; no allocation allowed) ----------
__device__ float g_xnt [(size_t)BATCH * HW * CH];   // x_norm^T [b][s][c]
__device__ float g_q   [(size_t)BATCH * HW * CH];   // [b][s][c]
__device__ float g_k   [(size_t)BATCH * HW * CH];   // [b][s][c]
__device__ float g_vt  [(size_t)BATCH * HW * CH];   // [b][t][c]
__device__ float g_v   [(size_t)BATCH * CH * HW];   // [b][c][t]
__device__ float g_attn[(size_t)BATCH * HW * HW];   // [b][s][t]
__device__ float g_ao  [(size_t)BATCH * HW * CH];   // [b][s][c]

// ---------------- helpers ----------------------------------------------------
__device__ __forceinline__ uint32_t smem_u32(const void* p) {
    uint32_t a;
    asm("{ .reg .u64 t; cvta.to.shared.u64 t, %1; cvt.u32.u64 %0, t; }" : "=r"(a) : "l"(p));
    return a;
}

__device__ __forceinline__ void ldsm4(uint32_t* r, uint32_t addr) {
    asm volatile("ldmatrix.sync.aligned.m8n8.x4.shared.b16 {%0,%1,%2,%3}, [%4];"
        : "=r"(r[0]), "=r"(r[1]), "=r"(r[2]), "=r"(r[3]) : "r"(addr));
}

__device__ __forceinline__ void mma16816(float* c, const uint32_t* a, uint32_t b0, uint32_t b1) {
    asm volatile("mma.sync.aligned.m16n8k16.row.col.f32.bf16.bf16.f32 "
        "{%0,%1,%2,%3}, {%4,%5,%6,%7}, {%8,%9}, {%0,%1,%2,%3};"
        : "+f"(c[0]), "+f"(c[1]), "+f"(c[2]), "+f"(c[3])
        : "r"(a[0]), "r"(a[1]), "r"(a[2]), "r"(a[3]), "r"(b0), "r"(b1));
}

// split fp32 -> bf16 hi/lo, store 4 elements (8B each) into padded smem
__device__ __forceinline__ void cvt_store(float4 v, __nv_bfloat16* hi, __nv_bfloat16* lo, int off) {
    __nv_bfloat162 h01 = __floats2bfloat162_rn(v.x, v.y);
    __nv_bfloat162 h23 = __floats2bfloat162_rn(v.z, v.w);
    float lx = v.x - __bfloat162float(h01.x);
    float ly = v.y - __bfloat162float(h01.y);
    float lz = v.z - __bfloat162float(h23.x);
    float lw = v.w - __bfloat162float(h23.y);
    __nv_bfloat162 l01 = __floats2bfloat162_rn(lx, ly);
    __nv_bfloat162 l23 = __floats2bfloat162_rn(lz, lw);
    uint2 hv, lv;
    hv.x = *(uint32_t*)&h01; hv.y = *(uint32_t*)&h23;
    lv.x = *(uint32_t*)&l01; lv.y = *(uint32_t*)&l23;
    *(uint2*)(hi + off) = hv;
    *(uint2*)(lo + off) = lv;
}

__device__ __forceinline__ void st2(float* p, float x, float y) {
    float2 v; v.x = x; v.y = y; *(float2*)p = v;
}

// ---------------- unified HMMA GEMM (double-buffered) ------------------------
// D[m][n] = sum_k A[m][k]*B[n][k], K-major fp32 operands split into bf16 hi/lo.
// MODE 0: A=xnt[s][c],  B=w_qkv[o][c], K=256  -> q/k/vt [s|t][c] + bias
// MODE 1: A=q[s][c],    B=k[t][c],    K=256  -> attn[s][t] * SCALE
// MODE 2: A=attn[s][t], B=v[c][t],    K=1024 -> ao[s][c]
// MODE 3: A=w_out[o][c],B=ao[s][c],   K=256  -> out[o][s] + bias + resid
#define LDS   40                 // padded bf16 row stride (80B)
#define ARR   (128 * LDS)        // elems per array (5120)
#define BUFE  (4 * ARR)          // elems per buffer (Ah,Al,Bh,Bl)
#define BUFB  (BUFE * 2)         // bytes per buffer (40960)
#define SMEMB (2 * BUFB)         // total dynamic smem (81920)

template <int MODE>
__global__ void __launch_bounds__(512, 1) mma_gemm(
    const float* __restrict__ W, const float* __restrict__ bias,
    const float* __restrict__ resid, float* __restrict__ Cout)
{
    constexpr int KTOT = (MODE == 2) ? 1024 : 256;
    constexpr int NCH = KTOT / 32;
    extern __shared__ __nv_bfloat16 dsm[];

    const int tid = threadIdx.x;
    const int lane = tid & 31, wid = tid >> 5;
    const int bz = blockIdx.z;
    const int bm = blockIdx.y * 128, bn = blockIdx.x * 128;

    const float *A, *B;
    if (MODE == 0) { A = g_xnt + (size_t)bz * HW * CH; B = W; }
    if (MODE == 1) { A = g_q + (size_t)bz * HW * CH;   B = g_k + (size_t)bz * HW * CH; }
    if (MODE == 2) { A = g_attn + (size_t)bz * HW * HW; B = g_v + (size_t)bz * CH * HW; }
    if (MODE == 3) { A = W; B = g_ao + (size_t)bz * HW * CH; }

    // staging: thread covers rows r0 and r0+64, 4 floats at col c0
    const int r0 = tid >> 3, c0 = (tid & 7) << 2;
    const float* Ar0 = A + (size_t)(bm + r0) * KTOT + c0;
    const float* Ar1 = Ar0 + (size_t)64 * KTOT;
    const float* Br0 = B + (size_t)(bn + r0) * KTOT + c0;
    const float* Br1 = Br0 + (size_t)64 * KTOT;
    const int so0 = r0 * LDS + c0, so1 = (r0 + 64) * LDS + c0;

    const int wm = (wid >> 2) * 32, wn = (wid & 3) * 32;

    // ldmatrix base addresses relative to buffer 0
    const uint32_t u0 = smem_u32(dsm);
    const int rowA = wm + (lane & 15);
    const int kOffA = (lane >> 4) << 3;
    const int rowB = wn + (lane & 7) + ((lane >> 4) << 3);
    const int kOffB = ((lane >> 3) & 1) << 3;
    uint32_t aHb[2], bHb[2];
#pragma unroll
    for (int mt = 0; mt < 2; mt++)
        aHb[mt] = u0 + (uint32_t)(((rowA + mt * 16) * LDS + kOffA) * 2);
#pragma unroll
    for (int p = 0; p < 2; p++)
        bHb[p] = u0 + (uint32_t)(((rowB + p * 16) * LDS + kOffB) * 2);
    const uint32_t dAl = ARR * 2, dBh = 2 * ARR * 2, dBl = 3 * ARR * 2;

    float acc[2][4][4] = {};

    // prologue: stage chunk 0 into buffer 0
    {
        float4 av0 = *(const float4*)Ar0;
        float4 av1 = *(const float4*)Ar1;
        float4 bv0 = *(const float4*)Br0;
        float4 bv1 = *(const float4*)Br1;
        __nv_bfloat16* ah = dsm;
        __nv_bfloat16* al = ah + ARR;
        __nv_bfloat16* bh = al + ARR;
        __nv_bfloat16* bl = bh + ARR;
        cvt_store(av0, ah, al, so0);
        cvt_store(av1, ah, al, so1);
        cvt_store(bv0, bh, bl, so0);
        cvt_store(bv1, bh, bl, so1);
    }
    __syncthreads();

    for (int ch = 0; ch < NCH; ch++) {
        const int cur = ch & 1;
        const uint32_t boff = (uint32_t)cur * BUFB;

        float4 av0, av1, bv0, bv1;
        if (ch + 1 < NCH) {                 // prefetch next chunk (LDG overlaps MMA)
            const int k = (ch + 1) * 32;
            av0 = *(const float4*)(Ar0 + k);
            av1 = *(const float4*)(Ar1 + k);
            bv0 = *(const float4*)(Br0 + k);
            bv1 = *(const float4*)(Br1 + k);
        }

#pragma unroll
        for (int ks = 0; ks < 2; ks++) {
            uint32_t ah[2][4], al[2][4], bh[2][4], bl[2][4];
#pragma unroll
            for (int mt = 0; mt < 2; mt++) {
                ldsm4(ah[mt], aHb[mt] + boff + ks * 32);
                ldsm4(al[mt], aHb[mt] + boff + dAl + ks * 32);
            }
#pragma unroll
            for (int p = 0; p < 2; p++) {
                ldsm4(bh[p], bHb[p] + boff + dBh + ks * 32);
                ldsm4(bl[p], bHb[p] + boff + dBl + ks * 32);
            }
#pragma unroll
            for (int mt = 0; mt < 2; mt++)
#pragma unroll
                for (int p = 0; p < 2; p++)
#pragma unroll
                    for (int h = 0; h < 2; h++) {
                        float* c = acc[mt][p * 2 + h];
                        mma16816(c, ah[mt], bh[p][h * 2], bh[p][h * 2 + 1]);
                        mma16816(c, ah[mt], bl[p][h * 2], bl[p][h * 2 + 1]);
                        mma16816(c, al[mt], bh[p][h * 2], bh[p][h * 2 + 1]);
                    }
        }

        if (ch + 1 < NCH) {                 // stage next chunk into other buffer
            __nv_bfloat16* ah = dsm + (1 - cur) * BUFE;
            __nv_bfloat16* al = ah + ARR;
            __nv_bfloat16* bh = al + ARR;
            __nv_bfloat16* bl = bh + ARR;
            cvt_store(av0, ah, al, so0);
            cvt_store(av1, ah, al, so1);
            cvt_store(bv0, bh, bl, so0);
            cvt_store(bv1, bh, bl, so1);
        }
        __syncthreads();
    }

    // ---------------- epilogue (n-contiguous float2 stores) -----------------
    const int gid = lane >> 2, qid = (lane & 3) * 2;

    if (MODE == 0) {
        const int bx = blockIdx.x;
        const int third = bx >> 1;
        const int cb = (bx & 1) * 128;
        float* dst = (third == 0 ? g_q : third == 1 ? g_k : g_vt) + (size_t)bz * HW * CH;
#pragma unroll
        for (int mt = 0; mt < 2; mt++) {
            const int s = bm + wm + mt * 16 + gid;
#pragma unroll
            for (int nt = 0; nt < 4; nt++) {
                const int cl = wn + nt * 8 + qid;
                const float b0v = bias[bx * 128 + cl];
                const float b1v = bias[bx * 128 + cl + 1];
                float* a = acc[mt][nt];
                st2(&dst[(size_t)s * CH + cb + cl], a[0] + b0v, a[1] + b1v);
                st2(&dst[(size_t)(s + 8) * CH + cb + cl], a[2] + b0v, a[3] + b1v);
            }
        }
    }
    if (MODE == 1) {
        float* dst = g_attn + (size_t)bz * HW * HW;
#pragma unroll
        for (int mt = 0; mt < 2; mt++) {
            const int s = bm + wm + mt * 16 + gid;
#pragma unroll
            for (int nt = 0; nt < 4; nt++) {
                const int t = bn + wn + nt * 8 + qid;
                float* a = acc[mt][nt];
                st2(&dst[(size_t)s * HW + t], a[0] * SCALE, a[1] * SCALE);
                st2(&dst[(size_t)(s + 8) * HW + t], a[2] * SCALE, a[3] * SCALE);
            }
        }
    }
    if (MODE == 2) {
        float* dst = g_ao + (size_t)bz * HW * CH;
#pragma unroll
        for (int mt = 0; mt < 2; mt++) {
            const int s = bm + wm + mt * 16 + gid;
#pragma unroll
            for (int nt = 0; nt < 4; nt++) {
                const int c = bn + wn + nt * 8 + qid;
                float* a = acc[mt][nt];
                st2(&dst[(size_t)s * CH + c], a[0], a[1]);
                st2(&dst[(size_t)(s + 8) * CH + c], a[2], a[3]);
            }
        }
    }
    if (MODE == 3) {
#pragma unroll
        for (int mt = 0; mt < 2; mt++) {
            const int o = bm + wm + mt * 16 + gid;
            const float bo0 = bias[o], bo8 = bias[o + 8];
#pragma unroll
            for (int nt = 0; nt < 4; nt++) {
                const int s = bn + wn + nt * 8 + qid;
                float* a = acc[mt][nt];
                size_t i0 = ((size_t)bz * CH + o) * HW + s;
                size_t i1 = ((size_t)bz * CH + o + 8) * HW + s;
                float2 rv0 = *(const float2*)&resid[i0];
                float2 rv1 = *(const float2*)&resid[i1];
                st2(&Cout[i0], a[0] + bo0 + rv0.x, a[1] + bo0 + rv0.y);
                st2(&Cout[i1], a[2] + bo8 + rv1.x, a[3] + bo8 + rv1.y);
            }
        }
    }
}

// ---------------- GroupNorm (writes x_norm^T [b][s][c]) ----------------------
__global__ void gn_kernel(const float* __restrict__ x,
                          const float* __restrict__ wt,
                          const float* __restrict__ bs)
{
    const int bg = blockIdx.x;              // b*8+g
    const int b = bg >> 3, g = bg & 7;
    const size_t base = (size_t)bg * (32 * HW);
    const int t = threadIdx.x;
    const float4* x4 = (const float4*)(x + base);

    float s = 0.f, s2 = 0.f;
#pragma unroll 4
    for (int i = t; i < 32 * HW / 4; i += 256) {
        float4 v = x4[i];
        s += v.x + v.y + v.z + v.w;
        s2 += v.x * v.x + v.y * v.y + v.z * v.z + v.w * v.w;
    }
    __shared__ float rs[256], rq[256];
    rs[t] = s; rq[t] = s2;
    __syncthreads();
    for (int o = 128; o > 0; o >>= 1) {
        if (t < o) { rs[t] += rs[t + o]; rq[t] += rq[t + o]; }
        __syncthreads();
    }
    __shared__ float s_m, s_r;
    if (t == 0) {
        float m = rs[0] * (1.0f / (32.f * HW));
        float v = rq[0] * (1.0f / (32.f * HW)) - m * m;
        s_m = m; s_r = rsqrtf(v + EPSV);
    }
    __syncthreads();
    __shared__ float cw[32], cb[32];
    if (t < 32) {
        float w = wt[g * 32 + t] * s_r;
        cw[t] = w;
        cb[t] = bs[g * 32 + t] - s_m * w;
    }
    __syncthreads();

    __shared__ float sm[32][33];
    const int row = t >> 5, col = t & 31;
    for (int s0 = 0; s0 < HW; s0 += 32) {
#pragma unroll
        for (int cr = 0; cr < 32; cr += 8) {
            int c = cr + row;
            sm[c][col] = x[base + (size_t)c * HW + s0 + col] * cw[c] + cb[c];
        }
        __syncthreads();
#pragma unroll
        for (int sr = 0; sr < 32; sr += 8) {
            int sl = sr + row;
            g_xnt[((size_t)b * HW + s0 + sl) * CH + g * 32 + col] = sm[col][sl];
        }
        __syncthreads();
    }
}

// ---------------- v transpose: vt[t][c] -> v[c][t] ---------------------------
__global__ void transpose_v()
{
    __shared__ float tile[32][33];
    const int b = blockIdx.z;
    const int t0 = blockIdx.x * 32;
    const int c0 = blockIdx.y * 32;
    const int x = threadIdx.x, y = threadIdx.y;
    const float* src = g_vt + (size_t)b * HW * CH;
    float* dst = g_v + (size_t)b * CH * HW;
#pragma unroll
    for (int j = 0; j < 32; j += 8)
        tile[y + j][x] = src[(size_t)(t0 + y + j) * CH + c0 + x];
    __syncthreads();
#pragma unroll
    for (int j = 0; j < 32; j += 8)
        dst[(size_t)(c0 + y + j) * HW + t0 + x] = tile[x][y + j];
}

// ---------------- softmax over last dim (1024) --------------------------------
__global__ void softmax_kernel()
{
    float* row = g_attn + (size_t)blockIdx.x * HW;
    const int t = threadIdx.x;
    float4 v = ((float4*)row)[t];

    float m = fmaxf(fmaxf(v.x, v.y), fmaxf(v.z, v.w));
#pragma unroll
    for (int o = 16; o > 0; o >>= 1) m = fmaxf(m, __shfl_xor_sync(0xffffffffu, m, o));
    __shared__ float red[8];
    if ((t & 31) == 0) red[t >> 5] = m;
    __syncthreads();
    float mm = red[0];
#pragma unroll
    for (int i = 1; i < 8; i++) mm = fmaxf(mm, red[i]);
    __syncthreads();

    float e0 = __expf(v.x - mm), e1 = __expf(v.y - mm);
    float e2 = __expf(v.z - mm), e3 = __expf(v.w - mm);
    float s = e0 + e1 + e2 + e3;
#pragma unroll
    for (int o = 16; o > 0; o >>= 1) s += __shfl_xor_sync(0xffffffffu, s, o);
    if ((t & 31) == 0) red[t >> 5] = s;
    __syncthreads();
    float tot = 0.f;
#pragma unroll
    for (int i = 0; i < 8; i++) tot += red[i];
    float inv = 1.0f / tot;

    float4 o4; o4.x = e0 * inv; o4.y = e1 * inv; o4.z = e2 * inv; o4.w = e3 * inv;
    ((float4*)row)[t] = o4;
}

// ---------------- launch -------------------------------------------------------
extern "C" void kernel_launch(void* const* d_in, const int* in_sizes, int n_in,
                              void* d_out, int out_size)
{
    const float* x    = (const float*)d_in[0];
    const float* gnw  = (const float*)d_in[1];
    const float* gnb  = (const float*)d_in[2];
    const float* wqkv = (const float*)d_in[3];
    const float* bqkv = (const float*)d_in[4];
    const float* wout = (const float*)d_in[5];
    const float* bout = (const float*)d_in[6];
    float* out = (float*)d_out;

    cudaFuncSetAttribute(mma_gemm<0>, cudaFuncAttributeMaxDynamicSharedMemorySize, SMEMB);
    cudaFuncSetAttribute(mma_gemm<1>, cudaFuncAttributeMaxDynamicSharedMemorySize, SMEMB);
    cudaFuncSetAttribute(mma_gemm<2>, cudaFuncAttributeMaxDynamicSharedMemorySize, SMEMB);
    cudaFuncSetAttribute(mma_gemm<3>, cudaFuncAttributeMaxDynamicSharedMemorySize, SMEMB);

    gn_kernel<<<BATCH * 8, 256>>>(x, gnw, gnb);
    mma_gemm<0><<<dim3(6, 8, BATCH), 512, SMEMB>>>(wqkv, bqkv, nullptr, nullptr);
    transpose_v<<<dim3(HW / 32, CH / 32, BATCH), dim3(32, 8)>>>();
    mma_gemm<1><<<dim3(8, 8, BATCH), 512, SMEMB>>>(nullptr, nullptr, nullptr, nullptr);
    softmax_kernel<<<BATCH * HW, 256>>>();
    mma_gemm<2><<<dim3(2, 8, BATCH), 512, SMEMB>>>(nullptr, nullptr, nullptr, nullptr);
    mma_gemm<3><<<dim3(8, 2, BATCH), 512, SMEMB>>>(wout, bout, x, out);
}

// round 5
// speedup vs baseline: 3.0081x; 1.0483x over previous
#include <cuda_runtime.h>
#include <cuda_bf16.h>
#include <cstdint>

#define BATCH 32
#define CH    256
#define HW    1024
#define EPSV  1e-5f
#define SCALE 0.0625f

// ---------------- scratch (device globals; no allocation allowed) ----------
__device__ float g_xnt [(size_t)BATCH * HW * CH];   // x_norm^T [b][s][c]
__device__ float g_q   [(size_t)BATCH * HW * CH];   // [b][s][c]
__device__ float g_k   [(size_t)BATCH * HW * CH];   // [b][s][c]
__device__ float g_vt  [(size_t)BATCH * HW * CH];   // [b][t][c]
__device__ float g_v   [(size_t)BATCH * CH * HW];   // [b][c][t]
__device__ float g_attn[(size_t)BATCH * HW * HW];   // [b][s][t]
__device__ float g_ao  [(size_t)BATCH * HW * CH];   // [b][s][c]

// ---------------- helpers ----------------------------------------------------
__device__ __forceinline__ uint32_t smem_u32(const void* p) {
    uint32_t a;
    asm("{ .reg .u64 t; cvta.to.shared.u64 t, %1; cvt.u32.u64 %0, t; }" : "=r"(a) : "l"(p));
    return a;
}

__device__ __forceinline__ void ldsm4(uint32_t* r, uint32_t addr) {
    asm volatile("ldmatrix.sync.aligned.m8n8.x4.shared.b16 {%0,%1,%2,%3}, [%4];"
        : "=r"(r[0]), "=r"(r[1]), "=r"(r[2]), "=r"(r[3]) : "r"(addr));
}

__device__ __forceinline__ void mma16816(float* c, const uint32_t* a, uint32_t b0, uint32_t b1) {
    asm volatile("mma.sync.aligned.m16n8k16.row.col.f32.bf16.bf16.f32 "
        "{%0,%1,%2,%3}, {%4,%5,%6,%7}, {%8,%9}, {%0,%1,%2,%3};"
        : "+f"(c[0]), "+f"(c[1]), "+f"(c[2]), "+f"(c[3])
        : "r"(a[0]), "r"(a[1]), "r"(a[2]), "r"(a[3]), "r"(b0), "r"(b1));
}

// split fp32 -> bf16 hi/lo, store 4 elements (8B each) into padded smem
__device__ __forceinline__ void cvt_store(float4 v, __nv_bfloat16* hi, __nv_bfloat16* lo, int off) {
    __nv_bfloat162 h01 = __floats2bfloat162_rn(v.x, v.y);
    __nv_bfloat162 h23 = __floats2bfloat162_rn(v.z, v.w);
    float lx = v.x - __bfloat162float(h01.x);
    float ly = v.y - __bfloat162float(h01.y);
    float lz = v.z - __bfloat162float(h23.x);
    float lw = v.w - __bfloat162float(h23.y);
    __nv_bfloat162 l01 = __floats2bfloat162_rn(lx, ly);
    __nv_bfloat162 l23 = __floats2bfloat162_rn(lz, lw);
    uint2 hv, lv;
    hv.x = *(uint32_t*)&h01; hv.y = *(uint32_t*)&h23;
    lv.x = *(uint32_t*)&l01; lv.y = *(uint32_t*)&l23;
    *(uint2*)(hi + off) = hv;
    *(uint2*)(lo + off) = lv;
}

__device__ __forceinline__ void st2(float* p, float x, float y) {
    float2 v; v.x = x; v.y = y; *(float2*)p = v;
}

// ---------------- unified HMMA GEMM (128x64 tile, 2 CTA/SM) ------------------
// D[m][n] = sum_k A[m][k]*B[n][k], K-major fp32 operands split into bf16 hi/lo.
// MODE 0: A=xnt[s][c],  B=w_qkv[o][c], K=256  -> q/k/vt [s|t][c] + bias
// MODE 1: A=q[s][c],    B=k[t][c],    K=256  -> attn[s][t] * SCALE
// MODE 2: A=attn[s][t], B=v[c][t],    K=1024 -> ao[s][c]
// MODE 3: A=w_out[o][c],B=ao[s][c],   K=256  -> out[o][s] + bias + resid
#define LDS    40                  // padded bf16 row stride (80B)
#define AELEM  (128 * LDS)         // 5120
#define BELEM  (64 * LDS)          // 2560
#define BUFE   (2 * AELEM + 2 * BELEM)  // 15360 elems
#define BUFB   (BUFE * 2)          // 30720 bytes
#define SMEMB  (2 * BUFB)          // 61440 bytes
#define OFF_AL (AELEM * 2)         // byte offsets within buffer
#define OFF_BH (2 * AELEM * 2)
#define OFF_BL (2 * AELEM * 2 + BELEM * 2)

template <int MODE>
__global__ void __launch_bounds__(256, 2) mma_gemm(
    const float* __restrict__ W, const float* __restrict__ bias,
    const float* __restrict__ resid, float* __restrict__ Cout)
{
    constexpr int KTOT = (MODE == 2) ? 1024 : 256;
    constexpr int NCH = KTOT / 32;
    extern __shared__ __nv_bfloat16 dsm[];

    const int tid = threadIdx.x;
    const int lane = tid & 31, wid = tid >> 5;
    const int bz = blockIdx.z;
    const int bm = blockIdx.y * 128, bn = blockIdx.x * 64;

    const float *A, *B;
    if (MODE == 0) { A = g_xnt + (size_t)bz * HW * CH; B = W; }
    if (MODE == 1) { A = g_q + (size_t)bz * HW * CH;   B = g_k + (size_t)bz * HW * CH; }
    if (MODE == 2) { A = g_attn + (size_t)bz * HW * HW; B = g_v + (size_t)bz * CH * HW; }
    if (MODE == 3) { A = W; B = g_ao + (size_t)bz * HW * CH; }

    // staging: r0 in 0..31, c0 covers 32 K cols; A rows r0+{0,32,64,96}, B rows r0+{0,32}
    const int r0 = tid >> 3, c0 = (tid & 7) << 2;
    const float* Ap = A + (size_t)(bm + r0) * KTOT + c0;
    const float* Bp = B + (size_t)(bn + r0) * KTOT + c0;
    const int soA = r0 * LDS + c0;

    const int wm = (wid >> 1) * 32, wn = (wid & 1) * 32;

    // ldmatrix base addresses relative to buffer 0
    const uint32_t u0 = smem_u32(dsm);
    const int rowA = wm + (lane & 15);
    const int kOffA = (lane >> 4) << 3;
    const int rowB = wn + (lane & 7) + ((lane >> 4) << 3);
    const int kOffB = ((lane >> 3) & 1) << 3;
    uint32_t aHb[2], bHb[2];
#pragma unroll
    for (int mt = 0; mt < 2; mt++)
        aHb[mt] = u0 + (uint32_t)(((rowA + mt * 16) * LDS + kOffA) * 2);
#pragma unroll
    for (int p = 0; p < 2; p++)
        bHb[p] = u0 + (uint32_t)OFF_BH + (uint32_t)(((rowB + p * 16) * LDS + kOffB) * 2);

    float acc[2][4][4] = {};

    // prologue: stage chunk 0 into buffer 0
    {
        __nv_bfloat16* ah = dsm;
        __nv_bfloat16* al = ah + AELEM;
        __nv_bfloat16* bh = al + AELEM;
        __nv_bfloat16* bl = bh + BELEM;
#pragma unroll
        for (int p = 0; p < 4; p++)
            cvt_store(*(const float4*)(Ap + (size_t)32 * p * KTOT), ah, al, soA + 32 * p * LDS);
#pragma unroll
        for (int p = 0; p < 2; p++)
            cvt_store(*(const float4*)(Bp + (size_t)32 * p * KTOT), bh, bl, soA + 32 * p * LDS);
    }
    __syncthreads();

    for (int ch = 0; ch < NCH; ch++) {
        const int cur = ch & 1;
        const uint32_t boff = (uint32_t)cur * BUFB;

        float4 av[4], bv[2];
        if (ch + 1 < NCH) {                 // prefetch next chunk (LDG overlaps MMA)
            const int k = (ch + 1) * 32;
#pragma unroll
            for (int p = 0; p < 4; p++) av[p] = *(const float4*)(Ap + (size_t)32 * p * KTOT + k);
#pragma unroll
            for (int p = 0; p < 2; p++) bv[p] = *(const float4*)(Bp + (size_t)32 * p * KTOT + k);
        }

#pragma unroll
        for (int ks = 0; ks < 2; ks++) {
            uint32_t ah[2][4], al[2][4], bh[2][4], bl[2][4];
#pragma unroll
            for (int mt = 0; mt < 2; mt++) {
                ldsm4(ah[mt], aHb[mt] + boff + ks * 32);
                ldsm4(al[mt], aHb[mt] + boff + OFF_AL + ks * 32);
            }
#pragma unroll
            for (int p = 0; p < 2; p++) {
                ldsm4(bh[p], bHb[p] + boff + ks * 32);
                ldsm4(bl[p], bHb[p] + boff + (OFF_BL - OFF_BH) + ks * 32);
            }
#pragma unroll
            for (int mt = 0; mt < 2; mt++)
#pragma unroll
                for (int p = 0; p < 2; p++)
#pragma unroll
                    for (int h = 0; h < 2; h++) {
                        float* c = acc[mt][p * 2 + h];
                        mma16816(c, ah[mt], bh[p][h * 2], bh[p][h * 2 + 1]);
                        mma16816(c, ah[mt], bl[p][h * 2], bl[p][h * 2 + 1]);
                        mma16816(c, al[mt], bh[p][h * 2], bh[p][h * 2 + 1]);
                    }
        }

        if (ch + 1 < NCH) {                 // stage next chunk into other buffer
            __nv_bfloat16* ah = dsm + (1 - cur) * BUFE;
            __nv_bfloat16* al = ah + AELEM;
            __nv_bfloat16* bh = al + AELEM;
            __nv_bfloat16* bl = bh + BELEM;
#pragma unroll
            for (int p = 0; p < 4; p++) cvt_store(av[p], ah, al, soA + 32 * p * LDS);
#pragma unroll
            for (int p = 0; p < 2; p++) cvt_store(bv[p], bh, bl, soA + 32 * p * LDS);
        }
        __syncthreads();
    }

    // ---------------- epilogue (n-contiguous float2 stores) -----------------
    const int gid = lane >> 2, qid = (lane & 3) * 2;

    if (MODE == 0) {
#pragma unroll
        for (int mt = 0; mt < 2; mt++) {
            const int s = bm + wm + mt * 16 + gid;
#pragma unroll
            for (int nt = 0; nt < 4; nt++) {
                const int oc = bn + wn + nt * 8 + qid;      // 0..767
                const int third = oc >> 8;
                const int cl = oc & 255;
                float* dst = (third == 0 ? g_q : third == 1 ? g_k : g_vt) + (size_t)bz * HW * CH;
                const float b0v = bias[oc];
                const float b1v = bias[oc + 1];
                float* a = acc[mt][nt];
                st2(&dst[(size_t)s * CH + cl], a[0] + b0v, a[1] + b1v);
                st2(&dst[(size_t)(s + 8) * CH + cl], a[2] + b0v, a[3] + b1v);
            }
        }
    }
    if (MODE == 1) {
        float* dst = g_attn + (size_t)bz * HW * HW;
#pragma unroll
        for (int mt = 0; mt < 2; mt++) {
            const int s = bm + wm + mt * 16 + gid;
#pragma unroll
            for (int nt = 0; nt < 4; nt++) {
                const int t = bn + wn + nt * 8 + qid;
                float* a = acc[mt][nt];
                st2(&dst[(size_t)s * HW + t], a[0] * SCALE, a[1] * SCALE);
                st2(&dst[(size_t)(s + 8) * HW + t], a[2] * SCALE, a[3] * SCALE);
            }
        }
    }
    if (MODE == 2) {
        float* dst = g_ao + (size_t)bz * HW * CH;
#pragma unroll
        for (int mt = 0; mt < 2; mt++) {
            const int s = bm + wm + mt * 16 + gid;
#pragma unroll
            for (int nt = 0; nt < 4; nt++) {
                const int c = bn + wn + nt * 8 + qid;
                float* a = acc[mt][nt];
                st2(&dst[(size_t)s * CH + c], a[0], a[1]);
                st2(&dst[(size_t)(s + 8) * CH + c], a[2], a[3]);
            }
        }
    }
    if (MODE == 3) {
#pragma unroll
        for (int mt = 0; mt < 2; mt++) {
            const int o = bm + wm + mt * 16 + gid;
            const float bo0 = bias[o], bo8 = bias[o + 8];
#pragma unroll
            for (int nt = 0; nt < 4; nt++) {
                const int s = bn + wn + nt * 8 + qid;
                float* a = acc[mt][nt];
                size_t i0 = ((size_t)bz * CH + o) * HW + s;
                size_t i1 = ((size_t)bz * CH + o + 8) * HW + s;
                float2 rv0 = *(const float2*)&resid[i0];
                float2 rv1 = *(const float2*)&resid[i1];
                st2(&Cout[i0], a[0] + bo0 + rv0.x, a[1] + bo0 + rv0.y);
                st2(&Cout[i1], a[2] + bo8 + rv1.x, a[3] + bo8 + rv1.y);
            }
        }
    }
}

// ---------------- GroupNorm (writes x_norm^T [b][s][c]) ----------------------
__global__ void gn_kernel(const float* __restrict__ x,
                          const float* __restrict__ wt,
                          const float* __restrict__ bs)
{
    const int bg = blockIdx.x;              // b*8+g
    const int b = bg >> 3, g = bg & 7;
    const size_t base = (size_t)bg * (32 * HW);
    const int t = threadIdx.x;
    const float4* x4 = (const float4*)(x + base);

    float s = 0.f, s2 = 0.f;
#pragma unroll 4
    for (int i = t; i < 32 * HW / 4; i += 256) {
        float4 v = x4[i];
        s += v.x + v.y + v.z + v.w;
        s2 += v.x * v.x + v.y * v.y + v.z * v.z + v.w * v.w;
    }
    __shared__ float rs[256], rq[256];
    rs[t] = s; rq[t] = s2;
    __syncthreads();
    for (int o = 128; o > 0; o >>= 1) {
        if (t < o) { rs[t] += rs[t + o]; rq[t] += rq[t + o]; }
        __syncthreads();
    }
    __shared__ float s_m, s_r;
    if (t == 0) {
        float m = rs[0] * (1.0f / (32.f * HW));
        float v = rq[0] * (1.0f / (32.f * HW)) - m * m;
        s_m = m; s_r = rsqrtf(v + EPSV);
    }
    __syncthreads();
    __shared__ float cw[32], cb[32];
    if (t < 32) {
        float w = wt[g * 32 + t] * s_r;
        cw[t] = w;
        cb[t] = bs[g * 32 + t] - s_m * w;
    }
    __syncthreads();

    __shared__ float sm[32][33];
    const int row = t >> 5, col = t & 31;
    for (int s0 = 0; s0 < HW; s0 += 32) {
#pragma unroll
        for (int cr = 0; cr < 32; cr += 8) {
            int c = cr + row;
            sm[c][col] = x[base + (size_t)c * HW + s0 + col] * cw[c] + cb[c];
        }
        __syncthreads();
#pragma unroll
        for (int sr = 0; sr < 32; sr += 8) {
            int sl = sr + row;
            g_xnt[((size_t)b * HW + s0 + sl) * CH + g * 32 + col] = sm[col][sl];
        }
        __syncthreads();
    }
}

// ---------------- v transpose: vt[t][c] -> v[c][t] ---------------------------
__global__ void transpose_v()
{
    __shared__ float tile[32][33];
    const int b = blockIdx.z;
    const int t0 = blockIdx.x * 32;
    const int c0 = blockIdx.y * 32;
    const int x = threadIdx.x, y = threadIdx.y;
    const float* src = g_vt + (size_t)b * HW * CH;
    float* dst = g_v + (size_t)b * CH * HW;
#pragma unroll
    for (int j = 0; j < 32; j += 8)
        tile[y + j][x] = src[(size_t)(t0 + y + j) * CH + c0 + x];
    __syncthreads();
#pragma unroll
    for (int j = 0; j < 32; j += 8)
        dst[(size_t)(c0 + y + j) * HW + t0 + x] = tile[x][y + j];
}

// ---------------- softmax over last dim (1024) --------------------------------
__global__ void softmax_kernel()
{
    float* row = g_attn + (size_t)blockIdx.x * HW;
    const int t = threadIdx.x;
    float4 v = ((float4*)row)[t];

    float m = fmaxf(fmaxf(v.x, v.y), fmaxf(v.z, v.w));
#pragma unroll
    for (int o = 16; o > 0; o >>= 1) m = fmaxf(m, __shfl_xor_sync(0xffffffffu, m, o));
    __shared__ float red[8];
    if ((t & 31) == 0) red[t >> 5] = m;
    __syncthreads();
    float mm = red[0];
#pragma unroll
    for (int i = 1; i < 8; i++) mm = fmaxf(mm, red[i]);
    __syncthreads();

    float e0 = __expf(v.x - mm), e1 = __expf(v.y - mm);
    float e2 = __expf(v.z - mm), e3 = __expf(v.w - mm);
    float s = e0 + e1 + e2 + e3;
#pragma unroll
    for (int o = 16; o > 0; o >>= 1) s += __shfl_xor_sync(0xffffffffu, s, o);
    if ((t & 31) == 0) red[t >> 5] = s;
    __syncthreads();
    float tot = 0.f;
#pragma unroll
    for (int i = 0; i < 8; i++) tot += red[i];
    float inv = 1.0f / tot;

    float4 o4; o4.x = e0 * inv; o4.y = e1 * inv; o4.z = e2 * inv; o4.w = e3 * inv;
    ((float4*)row)[t] = o4;
}

// ---------------- launch -------------------------------------------------------
extern "C" void kernel_launch(void* const* d_in, const int* in_sizes, int n_in,
                              void* d_out, int out_size)
{
    const float* x    = (const float*)d_in[0];
    const float* gnw  = (const float*)d_in[1];
    const float* gnb  = (const float*)d_in[2];
    const float* wqkv = (const float*)d_in[3];
    const float* bqkv = (const float*)d_in[4];
    const float* wout = (const float*)d_in[5];
    const float* bout = (const float*)d_in[6];
    float* out = (float*)d_out;

    cudaFuncSetAttribute(mma_gemm<0>, cudaFuncAttributeMaxDynamicSharedMemorySize, SMEMB);
    cudaFuncSetAttribute(mma_gemm<1>, cudaFuncAttributeMaxDynamicSharedMemorySize, SMEMB);
    cudaFuncSetAttribute(mma_gemm<2>, cudaFuncAttributeMaxDynamicSharedMemorySize, SMEMB);
    cudaFuncSetAttribute(mma_gemm<3>, cudaFuncAttributeMaxDynamicSharedMemorySize, SMEMB);

    gn_kernel<<<BATCH * 8, 256>>>(x, gnw, gnb);
    mma_gemm<0><<<dim3(12, 8, BATCH), 256, SMEMB>>>(wqkv, bqkv, nullptr, nullptr);
    transpose_v<<<dim3(HW / 32, CH / 32, BATCH), dim3(32, 8)>>>();
    mma_gemm<1><<<dim3(16, 8, BATCH), 256, SMEMB>>>(nullptr, nullptr, nullptr, nullptr);
    softmax_kernel<<<BATCH * HW, 256>>>();
    mma_gemm<2><<<dim3(4, 8, BATCH), 256, SMEMB>>>(nullptr, nullptr, nullptr, nullptr);
    mma_gemm<3><<<dim3(16, 2, BATCH), 256, SMEMB>>>(wout, bout, x, out);
}

// round 6
// speedup vs baseline: 3.5687x; 1.1864x over previous
#include <cuda_runtime.h>
#include <cuda_fp16.h>
#include <cstdint>

#define BATCH 32
#define CH    256
#define HW    1024
#define EPSV  1e-5f
#define SCALE 0.0625f

// ---------------- scratch (device globals; no allocation allowed) ----------
__device__ float g_xnt [(size_t)BATCH * HW * CH];   // x_norm^T [b][s][c]
__device__ float g_q   [(size_t)BATCH * HW * CH];   // [b][s][c]
__device__ float g_k   [(size_t)BATCH * HW * CH];   // [b][s][c]
__device__ float g_vt  [(size_t)BATCH * HW * CH];   // [b][t][c]
__device__ float g_v   [(size_t)BATCH * CH * HW];   // [b][c][t]
__device__ float g_attn[(size_t)BATCH * HW * HW];   // [b][s][t]
__device__ float g_ao  [(size_t)BATCH * HW * CH];   // [b][s][c]

// ---------------- helpers ----------------------------------------------------
__device__ __forceinline__ uint32_t smem_u32(const void* p) {
    uint32_t a;
    asm("{ .reg .u64 t; cvta.to.shared.u64 t, %1; cvt.u32.u64 %0, t; }" : "=r"(a) : "l"(p));
    return a;
}

__device__ __forceinline__ void ldsm4(uint32_t* r, uint32_t addr) {
    asm volatile("ldmatrix.sync.aligned.m8n8.x4.shared.b16 {%0,%1,%2,%3}, [%4];"
        : "=r"(r[0]), "=r"(r[1]), "=r"(r[2]), "=r"(r[3]) : "r"(addr));
}

__device__ __forceinline__ void mma16816(float* c, const uint32_t* a, uint32_t b0, uint32_t b1) {
    asm volatile("mma.sync.aligned.m16n8k16.row.col.f32.f16.f16.f32 "
        "{%0,%1,%2,%3}, {%4,%5,%6,%7}, {%8,%9}, {%0,%1,%2,%3};"
        : "+f"(c[0]), "+f"(c[1]), "+f"(c[2]), "+f"(c[3])
        : "r"(a[0]), "r"(a[1]), "r"(a[2]), "r"(a[3]), "r"(b0), "r"(b1));
}

// fp32 -> plain fp16, store 4 elements (8B)
__device__ __forceinline__ void cvt_store_a(float4 v, __half* dst, int off) {
    __half2 h01 = __floats2half2_rn(v.x, v.y);
    __half2 h23 = __floats2half2_rn(v.z, v.w);
    uint2 hv;
    hv.x = *(uint32_t*)&h01; hv.y = *(uint32_t*)&h23;
    *(uint2*)(dst + off) = hv;
}

// fp32 -> fp16 hi/lo split, store 4 elements each (8B each)
__device__ __forceinline__ void cvt_store_b(float4 v, __half* hi, __half* lo, int off) {
    __half2 h01 = __floats2half2_rn(v.x, v.y);
    __half2 h23 = __floats2half2_rn(v.z, v.w);
    float lx = v.x - __half2float(h01.x);
    float ly = v.y - __half2float(h01.y);
    float lz = v.z - __half2float(h23.x);
    float lw = v.w - __half2float(h23.y);
    __half2 l01 = __floats2half2_rn(lx, ly);
    __half2 l23 = __floats2half2_rn(lz, lw);
    uint2 hv, lv;
    hv.x = *(uint32_t*)&h01; hv.y = *(uint32_t*)&h23;
    lv.x = *(uint32_t*)&l01; lv.y = *(uint32_t*)&l23;
    *(uint2*)(hi + off) = hv;
    *(uint2*)(lo + off) = lv;
}

__device__ __forceinline__ void st2(float* p, float x, float y) {
    float2 v; v.x = x; v.y = y; *(float2*)p = v;
}

// ---------------- unified HMMA GEMM (128x64 tile, 2 CTA/SM) ------------------
// D[m][n] = sum_k A[m][k]*B[n][k]. A plain fp16, B split fp16 hi/lo (2 products).
// MODE 0: A=xnt[s][c],  B=w_qkv[o][c], K=256  -> q/k/vt [s|t][c] + bias
// MODE 1: A=q[s][c],    B=k[t][c],    K=256  -> attn[s][t] * SCALE
// MODE 2: A=attn[s][t], B=v[c][t],    K=1024 -> ao[s][c]
// MODE 3: A=w_out[o][c],B=ao[s][c],   K=256  -> out[o][s] + bias + resid
#define LDS    40                  // padded fp16 row stride (80B)
#define AELEM  (128 * LDS)         // 5120
#define BELEM  (64 * LDS)          // 2560
#define BUFE   (AELEM + 2 * BELEM) // 10240 elems
#define BUFB   (BUFE * 2)          // 20480 bytes
#define SMEMB  (2 * BUFB)          // 40960 bytes
#define OFF_BH (AELEM * 2)         // byte offsets within buffer
#define OFF_BL ((AELEM + BELEM) * 2)

template <int MODE>
__global__ void __launch_bounds__(256, 2) mma_gemm(
    const float* __restrict__ W, const float* __restrict__ bias,
    const float* __restrict__ resid, float* __restrict__ Cout)
{
    constexpr int KTOT = (MODE == 2) ? 1024 : 256;
    constexpr int NCH = KTOT / 32;
    extern __shared__ __half dsm[];

    const int tid = threadIdx.x;
    const int lane = tid & 31, wid = tid >> 5;
    const int bz = blockIdx.z;
    const int bm = blockIdx.y * 128, bn = blockIdx.x * 64;

    const float *A, *B;
    if (MODE == 0) { A = g_xnt + (size_t)bz * HW * CH; B = W; }
    if (MODE == 1) { A = g_q + (size_t)bz * HW * CH;   B = g_k + (size_t)bz * HW * CH; }
    if (MODE == 2) { A = g_attn + (size_t)bz * HW * HW; B = g_v + (size_t)bz * CH * HW; }
    if (MODE == 3) { A = W; B = g_ao + (size_t)bz * HW * CH; }

    // staging: r0 in 0..31, c0 covers 32 K cols; A rows r0+{0,32,64,96}, B rows r0+{0,32}
    const int r0 = tid >> 3, c0 = (tid & 7) << 2;
    const float* Ap = A + (size_t)(bm + r0) * KTOT + c0;
    const float* Bp = B + (size_t)(bn + r0) * KTOT + c0;
    const int soA = r0 * LDS + c0;

    const int wm = (wid >> 1) * 32, wn = (wid & 1) * 32;

    // ldmatrix base addresses relative to buffer 0
    const uint32_t u0 = smem_u32(dsm);
    const int rowA = wm + (lane & 15);
    const int kOffA = (lane >> 4) << 3;
    const int rowB = wn + (lane & 7) + ((lane >> 4) << 3);
    const int kOffB = ((lane >> 3) & 1) << 3;
    uint32_t aHb[2], bHb[2];
#pragma unroll
    for (int mt = 0; mt < 2; mt++)
        aHb[mt] = u0 + (uint32_t)(((rowA + mt * 16) * LDS + kOffA) * 2);
#pragma unroll
    for (int p = 0; p < 2; p++)
        bHb[p] = u0 + (uint32_t)OFF_BH + (uint32_t)(((rowB + p * 16) * LDS + kOffB) * 2);

    float acc[2][4][4] = {};

    // prologue: stage chunk 0 into buffer 0
    {
        __half* sa = dsm;
        __half* bh = dsm + AELEM;
        __half* bl = bh + BELEM;
#pragma unroll
        for (int p = 0; p < 4; p++)
            cvt_store_a(*(const float4*)(Ap + (size_t)32 * p * KTOT), sa, soA + 32 * p * LDS);
#pragma unroll
        for (int p = 0; p < 2; p++)
            cvt_store_b(*(const float4*)(Bp + (size_t)32 * p * KTOT), bh, bl, soA + 32 * p * LDS);
    }
    __syncthreads();

    for (int ch = 0; ch < NCH; ch++) {
        const int cur = ch & 1;
        const uint32_t boff = (uint32_t)cur * BUFB;

        float4 av[4], bv[2];
        if (ch + 1 < NCH) {                 // prefetch next chunk (LDG overlaps MMA)
            const int k = (ch + 1) * 32;
#pragma unroll
            for (int p = 0; p < 4; p++) av[p] = *(const float4*)(Ap + (size_t)32 * p * KTOT + k);
#pragma unroll
            for (int p = 0; p < 2; p++) bv[p] = *(const float4*)(Bp + (size_t)32 * p * KTOT + k);
        }

#pragma unroll
        for (int ks = 0; ks < 2; ks++) {
            uint32_t ah[2][4], bh[2][4], bl[2][4];
#pragma unroll
            for (int mt = 0; mt < 2; mt++)
                ldsm4(ah[mt], aHb[mt] + boff + ks * 32);
#pragma unroll
            for (int p = 0; p < 2; p++) {
                ldsm4(bh[p], bHb[p] + boff + ks * 32);
                ldsm4(bl[p], bHb[p] + boff + (OFF_BL - OFF_BH) + ks * 32);
            }
#pragma unroll
            for (int mt = 0; mt < 2; mt++)
#pragma unroll
                for (int p = 0; p < 2; p++)
#pragma unroll
                    for (int h = 0; h < 2; h++) {
                        float* c = acc[mt][p * 2 + h];
                        mma16816(c, ah[mt], bh[p][h * 2], bh[p][h * 2 + 1]);
                        mma16816(c, ah[mt], bl[p][h * 2], bl[p][h * 2 + 1]);
                    }
        }

        if (ch + 1 < NCH) {                 // stage next chunk into other buffer
            __half* sa = dsm + (1 - cur) * BUFE;
            __half* bh = sa + AELEM;
            __half* bl = bh + BELEM;
#pragma unroll
            for (int p = 0; p < 4; p++) cvt_store_a(av[p], sa, soA + 32 * p * LDS);
#pragma unroll
            for (int p = 0; p < 2; p++) cvt_store_b(bv[p], bh, bl, soA + 32 * p * LDS);
        }
        __syncthreads();
    }

    // ---------------- epilogue (n-contiguous float2 stores) -----------------
    const int gid = lane >> 2, qid = (lane & 3) * 2;

    if (MODE == 0) {
#pragma unroll
        for (int mt = 0; mt < 2; mt++) {
            const int s = bm + wm + mt * 16 + gid;
#pragma unroll
            for (int nt = 0; nt < 4; nt++) {
                const int oc = bn + wn + nt * 8 + qid;      // 0..767
                const int third = oc >> 8;
                const int cl = oc & 255;
                float* dst = (third == 0 ? g_q : third == 1 ? g_k : g_vt) + (size_t)bz * HW * CH;
                const float b0v = bias[oc];
                const float b1v = bias[oc + 1];
                float* a = acc[mt][nt];
                st2(&dst[(size_t)s * CH + cl], a[0] + b0v, a[1] + b1v);
                st2(&dst[(size_t)(s + 8) * CH + cl], a[2] + b0v, a[3] + b1v);
            }
        }
    }
    if (MODE == 1) {
        float* dst = g_attn + (size_t)bz * HW * HW;
#pragma unroll
        for (int mt = 0; mt < 2; mt++) {
            const int s = bm + wm + mt * 16 + gid;
#pragma unroll
            for (int nt = 0; nt < 4; nt++) {
                const int t = bn + wn + nt * 8 + qid;
                float* a = acc[mt][nt];
                st2(&dst[(size_t)s * HW + t], a[0] * SCALE, a[1] * SCALE);
                st2(&dst[(size_t)(s + 8) * HW + t], a[2] * SCALE, a[3] * SCALE);
            }
        }
    }
    if (MODE == 2) {
        float* dst = g_ao + (size_t)bz * HW * CH;
#pragma unroll
        for (int mt = 0; mt < 2; mt++) {
            const int s = bm + wm + mt * 16 + gid;
#pragma unroll
            for (int nt = 0; nt < 4; nt++) {
                const int c = bn + wn + nt * 8 + qid;
                float* a = acc[mt][nt];
                st2(&dst[(size_t)s * CH + c], a[0], a[1]);
                st2(&dst[(size_t)(s + 8) * CH + c], a[2], a[3]);
            }
        }
    }
    if (MODE == 3) {
#pragma unroll
        for (int mt = 0; mt < 2; mt++) {
            const int o = bm + wm + mt * 16 + gid;
            const float bo0 = bias[o], bo8 = bias[o + 8];
#pragma unroll
            for (int nt = 0; nt < 4; nt++) {
                const int s = bn + wn + nt * 8 + qid;
                float* a = acc[mt][nt];
                size_t i0 = ((size_t)bz * CH + o) * HW + s;
                size_t i1 = ((size_t)bz * CH + o + 8) * HW + s;
                float2 rv0 = *(const float2*)&resid[i0];
                float2 rv1 = *(const float2*)&resid[i1];
                st2(&Cout[i0], a[0] + bo0 + rv0.x, a[1] + bo0 + rv0.y);
                st2(&Cout[i1], a[2] + bo8 + rv1.x, a[3] + bo8 + rv1.y);
            }
        }
    }
}

// ---------------- GroupNorm (writes x_norm^T [b][s][c]) ----------------------
__global__ void gn_kernel(const float* __restrict__ x,
                          const float* __restrict__ wt,
                          const float* __restrict__ bs)
{
    const int bg = blockIdx.x;              // b*8+g
    const int b = bg >> 3, g = bg & 7;
    const size_t base = (size_t)bg * (32 * HW);
    const int t = threadIdx.x;
    const float4* x4 = (const float4*)(x + base);

    float s = 0.f, s2 = 0.f;
#pragma unroll 4
    for (int i = t; i < 32 * HW / 4; i += 256) {
        float4 v = x4[i];
        s += v.x + v.y + v.z + v.w;
        s2 += v.x * v.x + v.y * v.y + v.z * v.z + v.w * v.w;
    }
    __shared__ float rs[256], rq[256];
    rs[t] = s; rq[t] = s2;
    __syncthreads();
    for (int o = 128; o > 0; o >>= 1) {
        if (t < o) { rs[t] += rs[t + o]; rq[t] += rq[t + o]; }
        __syncthreads();
    }
    __shared__ float s_m, s_r;
    if (t == 0) {
        float m = rs[0] * (1.0f / (32.f * HW));
        float v = rq[0] * (1.0f / (32.f * HW)) - m * m;
        s_m = m; s_r = rsqrtf(v + EPSV);
    }
    __syncthreads();
    __shared__ float cw[32], cb[32];
    if (t < 32) {
        float w = wt[g * 32 + t] * s_r;
        cw[t] = w;
        cb[t] = bs[g * 32 + t] - s_m * w;
    }
    __syncthreads();

    __shared__ float sm[32][33];
    const int row = t >> 5, col = t & 31;
    for (int s0 = 0; s0 < HW; s0 += 32) {
#pragma unroll
        for (int cr = 0; cr < 32; cr += 8) {
            int c = cr + row;
            sm[c][col] = x[base + (size_t)c * HW + s0 + col] * cw[c] + cb[c];
        }
        __syncthreads();
#pragma unroll
        for (int sr = 0; sr < 32; sr += 8) {
            int sl = sr + row;
            g_xnt[((size_t)b * HW + s0 + sl) * CH + g * 32 + col] = sm[col][sl];
        }
        __syncthreads();
    }
}

// ---------------- v transpose: vt[t][c] -> v[c][t] ---------------------------
__global__ void transpose_v()
{
    __shared__ float tile[32][33];
    const int b = blockIdx.z;
    const int t0 = blockIdx.x * 32;
    const int c0 = blockIdx.y * 32;
    const int x = threadIdx.x, y = threadIdx.y;
    const float* src = g_vt + (size_t)b * HW * CH;
    float* dst = g_v + (size_t)b * CH * HW;
#pragma unroll
    for (int j = 0; j < 32; j += 8)
        tile[y + j][x] = src[(size_t)(t0 + y + j) * CH + c0 + x];
    __syncthreads();
#pragma unroll
    for (int j = 0; j < 32; j += 8)
        dst[(size_t)(c0 + y + j) * HW + t0 + x] = tile[x][y + j];
}

// ---------------- softmax over last dim (1024) --------------------------------
__global__ void softmax_kernel()
{
    float* row = g_attn + (size_t)blockIdx.x * HW;
    const int t = threadIdx.x;
    float4 v = ((float4*)row)[t];

    float m = fmaxf(fmaxf(v.x, v.y), fmaxf(v.z, v.w));
#pragma unroll
    for (int o = 16; o > 0; o >>= 1) m = fmaxf(m, __shfl_xor_sync(0xffffffffu, m, o));
    __shared__ float red[8];
    if ((t & 31) == 0) red[t >> 5] = m;
    __syncthreads();
    float mm = red[0];
#pragma unroll
    for (int i = 1; i < 8; i++) mm = fmaxf(mm, red[i]);
    __syncthreads();

    float e0 = __expf(v.x - mm), e1 = __expf(v.y - mm);
    float e2 = __expf(v.z - mm), e3 = __expf(v.w - mm);
    float s = e0 + e1 + e2 + e3;
#pragma unroll
    for (int o = 16; o > 0; o >>= 1) s += __shfl_xor_sync(0xffffffffu, s, o);
    if ((t & 31) == 0) red[t >> 5] = s;
    __syncthreads();
    float tot = 0.f;
#pragma unroll
    for (int i = 0; i < 8; i++) tot += red[i];
    float inv = 1.0f / tot;

    float4 o4; o4.x = e0 * inv; o4.y = e1 * inv; o4.z = e2 * inv; o4.w = e3 * inv;
    ((float4*)row)[t] = o4;
}

// ---------------- launch -------------------------------------------------------
extern "C" void kernel_launch(void* const* d_in, const int* in_sizes, int n_in,
                              void* d_out, int out_size)
{
    const float* x    = (const float*)d_in[0];
    const float* gnw  = (const float*)d_in[1];
    const float* gnb  = (const float*)d_in[2];
    const float* wqkv = (const float*)d_in[3];
    const float* bqkv = (const float*)d_in[4];
    const float* wout = (const float*)d_in[5];
    const float* bout = (const float*)d_in[6];
    float* out = (float*)d_out;

    cudaFuncSetAttribute(mma_gemm<0>, cudaFuncAttributeMaxDynamicSharedMemorySize, SMEMB);
    cudaFuncSetAttribute(mma_gemm<1>, cudaFuncAttributeMaxDynamicSharedMemorySize, SMEMB);
    cudaFuncSetAttribute(mma_gemm<2>, cudaFuncAttributeMaxDynamicSharedMemorySize, SMEMB);
    cudaFuncSetAttribute(mma_gemm<3>, cudaFuncAttributeMaxDynamicSharedMemorySize, SMEMB);

    gn_kernel<<<BATCH * 8, 256>>>(x, gnw, gnb);
    mma_gemm<0><<<dim3(12, 8, BATCH), 256, SMEMB>>>(wqkv, bqkv, nullptr, nullptr);
    transpose_v<<<dim3(HW / 32, CH / 32, BATCH), dim3(32, 8)>>>();
    mma_gemm<1><<<dim3(16, 8, BATCH), 256, SMEMB>>>(nullptr, nullptr, nullptr, nullptr);
    softmax_kernel<<<BATCH * HW, 256>>>();
    mma_gemm<2><<<dim3(4, 8, BATCH), 256, SMEMB>>>(nullptr, nullptr, nullptr, nullptr);
    mma_gemm<3><<<dim3(16, 2, BATCH), 256, SMEMB>>>(wout, bout, x, out);
}

// round 7
// speedup vs baseline: 4.3066x; 1.2068x over previous
#include <cuda_runtime.h>
#include <cuda_fp16.h>
#include <cstdint>

#define BATCH 32
#define CH    256
#define HW    1024
#define EPSV  1e-5f
#define SCALE 0.0625f

// ---------------- scratch (device globals; no allocation allowed) ----------
__device__ __align__(256) __half  g_hxnt[(size_t)BATCH * HW * CH];  // [b][s][c]
__device__ __align__(256) __half  g_qh  [(size_t)BATCH * HW * CH];  // [b][s][c]
__device__ __align__(256) __half  g_kh  [(size_t)BATCH * HW * CH];  // [b][t][c]
__device__ __align__(256) __half  g_kl  [(size_t)BATCH * HW * CH];
__device__ __align__(256) float   g_vt  [(size_t)BATCH * HW * CH];  // [b][t][c] fp32
__device__ __align__(256) __half  g_vh  [(size_t)BATCH * CH * HW];  // [b][c][t]
__device__ __align__(256) __half  g_vl  [(size_t)BATCH * CH * HW];
__device__ __align__(256) float   g_attn[(size_t)BATCH * HW * HW];  // fp32 scores
__device__ __align__(256) __half  g_ph  [(size_t)BATCH * HW * HW];  // fp16 probs
__device__ __align__(256) __half  g_aoh [(size_t)BATCH * HW * CH];  // [b][s][c]
__device__ __align__(256) __half  g_aol [(size_t)BATCH * HW * CH];
__device__ __align__(256) __half  g_wqh [3 * CH * CH];
__device__ __align__(256) __half  g_wql [3 * CH * CH];
__device__ __align__(256) __half  g_woh [CH * CH];

// ---------------- helpers ----------------------------------------------------
__device__ __forceinline__ uint32_t smem_u32(const void* p) {
    uint32_t a;
    asm("{ .reg .u64 t; cvta.to.shared.u64 t, %1; cvt.u32.u64 %0, t; }" : "=r"(a) : "l"(p));
    return a;
}

__device__ __forceinline__ void ldsm4(uint32_t* r, uint32_t addr) {
    asm volatile("ldmatrix.sync.aligned.m8n8.x4.shared.b16 {%0,%1,%2,%3}, [%4];"
        : "=r"(r[0]), "=r"(r[1]), "=r"(r[2]), "=r"(r[3]) : "r"(addr));
}

__device__ __forceinline__ void mma16816(float* c, const uint32_t* a, uint32_t b0, uint32_t b1) {
    asm volatile("mma.sync.aligned.m16n8k16.row.col.f32.f16.f16.f32 "
        "{%0,%1,%2,%3}, {%4,%5,%6,%7}, {%8,%9}, {%0,%1,%2,%3};"
        : "+f"(c[0]), "+f"(c[1]), "+f"(c[2]), "+f"(c[3])
        : "r"(a[0]), "r"(a[1]), "r"(a[2]), "r"(a[3]), "r"(b0), "r"(b1));
}

#define CP16(dst, src) \
    asm volatile("cp.async.cg.shared.global [%0], [%1], 16;" :: "r"(dst), "l"(src))
#define CPCOMMIT() asm volatile("cp.async.commit_group;" ::: "memory")
#define CPWAIT1()  asm volatile("cp.async.wait_group 1;"  ::: "memory")

__device__ __forceinline__ void st2(float* p, float x, float y) {
    float2 v; v.x = x; v.y = y; *(float2*)p = v;
}
__device__ __forceinline__ void sth2(__half* p, float x, float y) {
    *(__half2*)p = __floats2half2_rn(x, y);
}
__device__ __forceinline__ void split_st(__half* hp, __half* lp, size_t i, float x, float y) {
    __half2 h = __floats2half2_rn(x, y);
    float lx = x - __half2float(h.x), ly = y - __half2float(h.y);
    *(__half2*)(hp + i) = h;
    *(__half2*)(lp + i) = __floats2half2_rn(lx, ly);
}

// ---------------- unified HMMA GEMM (128x64 tile, cp.async 3-stage) ----------
// D[m][n] = sum_k A[m][k]*B[n][k]. A plain fp16, B split fp16 hi/lo.
// MODE 0: A=hxnt[s][c], B=wq h/l,     K=256  -> q_h / k_h,k_l / vt(fp32) + bias
// MODE 1: A=q_h[s][c],  B=k h/l[t][c],K=256  -> attn[s][t]*SCALE (fp32)
// MODE 2: A=p_h[s][t],  B=v h/l[c][t],K=1024 -> ao h/l [s][c]
// MODE 3: A=woh[o][c],  B=ao h/l[s][c],K=256 -> out[o][s] + bias + resid
#define LDS    40                  // padded fp16 row stride (80B)
#define AELEM  (128 * LDS)         // 5120 halfs
#define BELEM  (64 * LDS)          // 2560 halfs
#define OFF_BH (AELEM * 2)         // 10240 B
#define OFF_BL ((AELEM + BELEM) * 2)
#define STAGEB ((AELEM + 2 * BELEM) * 2)   // 20480 B
#define SMEMB  (3 * STAGEB)                // 61440 B

template <int KTOT>
__device__ __forceinline__ void stage_chunk(
    const __half* __restrict__ Ap, const __half* __restrict__ Bph,
    const __half* __restrict__ Bpl, uint32_t sbuf, int tid, int k0)
{
#pragma unroll
    for (int s = 0; s < 2; s++) {
        const int slot = tid + s * 256;
        const int row = slot >> 2, seg = slot & 3;
        CP16(sbuf + (uint32_t)((row * LDS + seg * 8) * 2),
             Ap + (size_t)row * KTOT + k0 + seg * 8);
    }
    {
        const int row = tid >> 2, seg = tid & 3;
        const uint32_t d = (uint32_t)((row * LDS + seg * 8) * 2);
        const size_t  g = (size_t)row * KTOT + k0 + seg * 8;
        CP16(sbuf + OFF_BH + d, Bph + g);
        CP16(sbuf + OFF_BL + d, Bpl + g);
    }
}

template <int MODE>
__global__ void __launch_bounds__(256, 2) mma_gemm(
    const float* __restrict__ bias,
    const float* __restrict__ resid, float* __restrict__ Cout)
{
    constexpr int KTOT = (MODE == 2) ? 1024 : 256;
    constexpr int NCH = KTOT / 32;
    extern __shared__ __half dsm[];

    const int tid = threadIdx.x;
    const int lane = tid & 31, wid = tid >> 5;
    const int bz = blockIdx.z;
    const int bm = blockIdx.y * 128, bn = blockIdx.x * 64;

    const __half *Ah, *Bh, *Bl;
    if (MODE == 0) { Ah = g_hxnt + (size_t)bz * HW * CH; Bh = g_wqh; Bl = g_wql; }
    if (MODE == 1) { Ah = g_qh + (size_t)bz * HW * CH;   Bh = g_kh + (size_t)bz * HW * CH; Bl = g_kl + (size_t)bz * HW * CH; }
    if (MODE == 2) { Ah = g_ph + (size_t)bz * HW * HW;   Bh = g_vh + (size_t)bz * CH * HW; Bl = g_vl + (size_t)bz * CH * HW; }
    if (MODE == 3) { Ah = g_woh;                          Bh = g_aoh + (size_t)bz * HW * CH; Bl = g_aol + (size_t)bz * HW * CH; }

    const __half* Ap  = Ah + (size_t)bm * KTOT;
    const __half* Bph = Bh + (size_t)bn * KTOT;
    const __half* Bpl = Bl + (size_t)bn * KTOT;

    const int wm = (wid >> 1) * 32, wn = (wid & 1) * 32;

    // ldmatrix base addresses relative to stage 0
    const uint32_t u0 = smem_u32(dsm);
    const int rowA = wm + (lane & 15);
    const int kOffA = (lane >> 4) << 3;
    const int rowB = wn + (lane & 7) + ((lane >> 4) << 3);
    const int kOffB = ((lane >> 3) & 1) << 3;
    uint32_t aHb[2], bHb[2];
#pragma unroll
    for (int mt = 0; mt < 2; mt++)
        aHb[mt] = u0 + (uint32_t)(((rowA + mt * 16) * LDS + kOffA) * 2);
#pragma unroll
    for (int p = 0; p < 2; p++)
        bHb[p] = u0 + (uint32_t)OFF_BH + (uint32_t)(((rowB + p * 16) * LDS + kOffB) * 2);

    float acc[2][4][4] = {};

    // prologue: issue chunks 0 and 1
    stage_chunk<KTOT>(Ap, Bph, Bpl, u0, tid, 0);
    CPCOMMIT();
    stage_chunk<KTOT>(Ap, Bph, Bpl, u0 + STAGEB, tid, 32);
    CPCOMMIT();

    for (int ch = 0; ch < NCH; ch++) {
        CPWAIT1();                 // chunk ch resident
        __syncthreads();
        if (ch + 2 < NCH) {
            const int nb = (ch + 2) % 3;
            stage_chunk<KTOT>(Ap, Bph, Bpl, u0 + nb * STAGEB, tid, (ch + 2) * 32);
        }
        CPCOMMIT();                // always commit (possibly empty) to keep counts uniform

        const uint32_t boff = (uint32_t)((ch % 3) * STAGEB);
#pragma unroll
        for (int ks = 0; ks < 2; ks++) {
            uint32_t ahf[2][4], bhf[2][4], blf[2][4];
#pragma unroll
            for (int mt = 0; mt < 2; mt++)
                ldsm4(ahf[mt], aHb[mt] + boff + ks * 32);
#pragma unroll
            for (int p = 0; p < 2; p++) {
                ldsm4(bhf[p], bHb[p] + boff + ks * 32);
                ldsm4(blf[p], bHb[p] + boff + (OFF_BL - OFF_BH) + ks * 32);
            }
#pragma unroll
            for (int mt = 0; mt < 2; mt++)
#pragma unroll
                for (int p = 0; p < 2; p++)
#pragma unroll
                    for (int h = 0; h < 2; h++) {
                        float* c = acc[mt][p * 2 + h];
                        mma16816(c, ahf[mt], bhf[p][h * 2], bhf[p][h * 2 + 1]);
                        mma16816(c, ahf[mt], blf[p][h * 2], blf[p][h * 2 + 1]);
                    }
        }
    }

    // ---------------- epilogue -----------------------------------------------
    const int gid = lane >> 2, qid = (lane & 3) * 2;

    if (MODE == 0) {
#pragma unroll
        for (int mt = 0; mt < 2; mt++) {
            const int s = bm + wm + mt * 16 + gid;
#pragma unroll
            for (int nt = 0; nt < 4; nt++) {
                const int oc = bn + wn + nt * 8 + qid;      // 0..767
                const int third = oc >> 8;
                const int cl = oc & 255;
                const float b0v = bias[oc], b1v = bias[oc + 1];
                float* a = acc[mt][nt];
                const float v0 = a[0] + b0v, v1 = a[1] + b1v;
                const float v2 = a[2] + b0v, v3 = a[3] + b1v;
                const size_t i0 = ((size_t)bz * HW + s) * CH + cl;
                const size_t i1 = ((size_t)bz * HW + s + 8) * CH + cl;
                if (third == 0) {
                    sth2(&g_qh[i0], v0, v1);
                    sth2(&g_qh[i1], v2, v3);
                } else if (third == 1) {
                    split_st(g_kh, g_kl, i0, v0, v1);
                    split_st(g_kh, g_kl, i1, v2, v3);
                } else {
                    st2(&g_vt[i0], v0, v1);
                    st2(&g_vt[i1], v2, v3);
                }
            }
        }
    }
    if (MODE == 1) {
        float* dst = g_attn + (size_t)bz * HW * HW;
#pragma unroll
        for (int mt = 0; mt < 2; mt++) {
            const int s = bm + wm + mt * 16 + gid;
#pragma unroll
            for (int nt = 0; nt < 4; nt++) {
                const int t = bn + wn + nt * 8 + qid;
                float* a = acc[mt][nt];
                st2(&dst[(size_t)s * HW + t], a[0] * SCALE, a[1] * SCALE);
                st2(&dst[(size_t)(s + 8) * HW + t], a[2] * SCALE, a[3] * SCALE);
            }
        }
    }
    if (MODE == 2) {
#pragma unroll
        for (int mt = 0; mt < 2; mt++) {
            const int s = bm + wm + mt * 16 + gid;
#pragma unroll
            for (int nt = 0; nt < 4; nt++) {
                const int c = bn + wn + nt * 8 + qid;
                float* a = acc[mt][nt];
                const size_t i0 = ((size_t)bz * HW + s) * CH + c;
                const size_t i1 = ((size_t)bz * HW + s + 8) * CH + c;
                split_st(g_aoh, g_aol, i0, a[0], a[1]);
                split_st(g_aoh, g_aol, i1, a[2], a[3]);
            }
        }
    }
    if (MODE == 3) {
#pragma unroll
        for (int mt = 0; mt < 2; mt++) {
            const int o = bm + wm + mt * 16 + gid;
            const float bo0 = bias[o], bo8 = bias[o + 8];
#pragma unroll
            for (int nt = 0; nt < 4; nt++) {
                const int s = bn + wn + nt * 8 + qid;
                float* a = acc[mt][nt];
                size_t i0 = ((size_t)bz * CH + o) * HW + s;
                size_t i1 = ((size_t)bz * CH + o + 8) * HW + s;
                float2 rv0 = *(const float2*)&resid[i0];
                float2 rv1 = *(const float2*)&resid[i1];
                st2(&Cout[i0], a[0] + bo0 + rv0.x, a[1] + bo0 + rv0.y);
                st2(&Cout[i1], a[2] + bo8 + rv1.x, a[3] + bo8 + rv1.y);
            }
        }
    }
}

// ---------------- weight conversion ------------------------------------------
__global__ void convert_w(const float* __restrict__ wqkv, const float* __restrict__ wout)
{
    const int i = blockIdx.x * 256 + threadIdx.x;
    if (i < 3 * CH * CH) {
        float v = wqkv[i];
        __half h = __float2half_rn(v);
        g_wqh[i] = h;
        g_wql[i] = __float2half_rn(v - __half2float(h));
    }
    if (i < CH * CH)
        g_woh[i] = __float2half_rn(wout[i]);
}

// ---------------- GroupNorm (writes x_norm^T [b][s][c] fp16) ------------------
__global__ void gn_kernel(const float* __restrict__ x,
                          const float* __restrict__ wt,
                          const float* __restrict__ bs)
{
    const int bg = blockIdx.x;              // b*8+g
    const int b = bg >> 3, g = bg & 7;
    const size_t base = (size_t)bg * (32 * HW);
    const int t = threadIdx.x;
    const float4* x4 = (const float4*)(x + base);

    float s = 0.f, s2 = 0.f;
#pragma unroll 4
    for (int i = t; i < 32 * HW / 4; i += 256) {
        float4 v = x4[i];
        s += v.x + v.y + v.z + v.w;
        s2 += v.x * v.x + v.y * v.y + v.z * v.z + v.w * v.w;
    }
    __shared__ float rs[256], rq[256];
    rs[t] = s; rq[t] = s2;
    __syncthreads();
    for (int o = 128; o > 0; o >>= 1) {
        if (t < o) { rs[t] += rs[t + o]; rq[t] += rq[t + o]; }
        __syncthreads();
    }
    __shared__ float s_m, s_r;
    if (t == 0) {
        float m = rs[0] * (1.0f / (32.f * HW));
        float v = rq[0] * (1.0f / (32.f * HW)) - m * m;
        s_m = m; s_r = rsqrtf(v + EPSV);
    }
    __syncthreads();
    __shared__ float cw[32], cb[32];
    if (t < 32) {
        float w = wt[g * 32 + t] * s_r;
        cw[t] = w;
        cb[t] = bs[g * 32 + t] - s_m * w;
    }
    __syncthreads();

    __shared__ float sm[32][33];
    const int row = t >> 5, col = t & 31;
    for (int s0 = 0; s0 < HW; s0 += 32) {
#pragma unroll
        for (int cr = 0; cr < 32; cr += 8) {
            int c = cr + row;
            sm[c][col] = x[base + (size_t)c * HW + s0 + col] * cw[c] + cb[c];
        }
        __syncthreads();
#pragma unroll
        for (int sr = 0; sr < 32; sr += 8) {
            int sl = sr + row;
            g_hxnt[((size_t)b * HW + s0 + sl) * CH + g * 32 + col] =
                __float2half_rn(sm[col][sl]);
        }
        __syncthreads();
    }
}

// ---------------- v transpose + split: vt[t][c] fp32 -> v_h/v_l[c][t] ---------
__global__ void transpose_v()
{
    __shared__ float tile[32][33];
    const int b = blockIdx.z;
    const int t0 = blockIdx.x * 32;
    const int c0 = blockIdx.y * 32;
    const int x = threadIdx.x, y = threadIdx.y;
    const float* src = g_vt + (size_t)b * HW * CH;
    __half* dsh = g_vh + (size_t)b * CH * HW;
    __half* dsl = g_vl + (size_t)b * CH * HW;
#pragma unroll
    for (int j = 0; j < 32; j += 8)
        tile[y + j][x] = src[(size_t)(t0 + y + j) * CH + c0 + x];
    __syncthreads();
#pragma unroll
    for (int j = 0; j < 32; j += 8) {
        const float v = tile[x][y + j];
        const __half h = __float2half_rn(v);
        const size_t idx = (size_t)(c0 + y + j) * HW + t0 + x;
        dsh[idx] = h;
        dsl[idx] = __float2half_rn(v - __half2float(h));
    }
}

// ---------------- softmax (fp32 scores -> fp16 probs) -------------------------
__global__ void softmax_kernel()
{
    const float* row = g_attn + (size_t)blockIdx.x * HW;
    __half* orow = g_ph + (size_t)blockIdx.x * HW;
    const int t = threadIdx.x;
    float4 v = ((const float4*)row)[t];

    float m = fmaxf(fmaxf(v.x, v.y), fmaxf(v.z, v.w));
#pragma unroll
    for (int o = 16; o > 0; o >>= 1) m = fmaxf(m, __shfl_xor_sync(0xffffffffu, m, o));
    __shared__ float red[8];
    if ((t & 31) == 0) red[t >> 5] = m;
    __syncthreads();
    float mm = red[0];
#pragma unroll
    for (int i = 1; i < 8; i++) mm = fmaxf(mm, red[i]);
    __syncthreads();

    float e0 = __expf(v.x - mm), e1 = __expf(v.y - mm);
    float e2 = __expf(v.z - mm), e3 = __expf(v.w - mm);
    float s = e0 + e1 + e2 + e3;
#pragma unroll
    for (int o = 16; o > 0; o >>= 1) s += __shfl_xor_sync(0xffffffffu, s, o);
    if ((t & 31) == 0) red[t >> 5] = s;
    __syncthreads();
    float tot = 0.f;
#pragma unroll
    for (int i = 0; i < 8; i++) tot += red[i];
    float inv = 1.0f / tot;

    uint2 pk;
    __half2 p01 = __floats2half2_rn(e0 * inv, e1 * inv);
    __half2 p23 = __floats2half2_rn(e2 * inv, e3 * inv);
    pk.x = *(uint32_t*)&p01; pk.y = *(uint32_t*)&p23;
    *(uint2*)(orow + t * 4) = pk;
}

// ---------------- launch -------------------------------------------------------
extern "C" void kernel_launch(void* const* d_in, const int* in_sizes, int n_in,
                              void* d_out, int out_size)
{
    const float* x    = (const float*)d_in[0];
    const float* gnw  = (const float*)d_in[1];
    const float* gnb  = (const float*)d_in[2];
    const float* wqkv = (const float*)d_in[3];
    const float* bqkv = (const float*)d_in[4];
    const float* wout = (const float*)d_in[5];
    const float* bout = (const float*)d_in[6];
    float* out = (float*)d_out;

    cudaFuncSetAttribute(mma_gemm<0>, cudaFuncAttributeMaxDynamicSharedMemorySize, SMEMB);
    cudaFuncSetAttribute(mma_gemm<1>, cudaFuncAttributeMaxDynamicSharedMemorySize, SMEMB);
    cudaFuncSetAttribute(mma_gemm<2>, cudaFuncAttributeMaxDynamicSharedMemorySize, SMEMB);
    cudaFuncSetAttribute(mma_gemm<3>, cudaFuncAttributeMaxDynamicSharedMemorySize, SMEMB);

    convert_w<<<(3 * CH * CH + 255) / 256, 256>>>(wqkv, wout);
    gn_kernel<<<BATCH * 8, 256>>>(x, gnw, gnb);
    mma_gemm<0><<<dim3(12, 8, BATCH), 256, SMEMB>>>(bqkv, nullptr, nullptr);
    transpose_v<<<dim3(HW / 32, CH / 32, BATCH), dim3(32, 8)>>>();
    mma_gemm<1><<<dim3(16, 8, BATCH), 256, SMEMB>>>(nullptr, nullptr, nullptr);
    softmax_kernel<<<BATCH * HW, 256>>>();
    mma_gemm<2><<<dim3(4, 8, BATCH), 256, SMEMB>>>(nullptr, nullptr, nullptr);
    mma_gemm<3><<<dim3(16, 2, BATCH), 256, SMEMB>>>(bout, x, out);
}

// round 8
// speedup vs baseline: 5.3052x; 1.2319x over previous
#include <cuda_runtime.h>
#include <cuda_fp16.h>
#include <cstdint>

#define BATCH 32
#define CH    256
#define HW    1024
#define EPSV  1e-5f
#define SCALE 0.0625f

// ---------------- scratch (device globals; no allocation allowed) ----------
__device__ __align__(256) __half  g_hxnt[(size_t)BATCH * HW * CH];  // [b][s][c]
__device__ __align__(256) __half  g_qh  [(size_t)BATCH * HW * CH];  // [b][s][c]
__device__ __align__(256) __half  g_kh  [(size_t)BATCH * HW * CH];  // [b][t][c]
__device__ __align__(256) __half  g_vh  [(size_t)BATCH * CH * HW];  // [b][c][t]
__device__ __align__(256) float   g_attn[(size_t)BATCH * HW * HW];  // fp32 scores
__device__ __align__(256) __half  g_ph  [(size_t)BATCH * HW * HW];  // fp16 probs
__device__ __align__(256) __half  g_aoh [(size_t)BATCH * HW * CH];  // [b][s][c]
__device__ __align__(256) __half  g_aol [(size_t)BATCH * HW * CH];
__device__ __align__(256) __half  g_wqh [3 * CH * CH];
__device__ __align__(256) __half  g_wql [3 * CH * CH];
__device__ __align__(256) __half  g_woh [CH * CH];

// ---------------- helpers ----------------------------------------------------
__device__ __forceinline__ uint32_t smem_u32(const void* p) {
    uint32_t a;
    asm("{ .reg .u64 t; cvta.to.shared.u64 t, %1; cvt.u32.u64 %0, t; }" : "=r"(a) : "l"(p));
    return a;
}

__device__ __forceinline__ void ldsm4(uint32_t* r, uint32_t addr) {
    asm volatile("ldmatrix.sync.aligned.m8n8.x4.shared.b16 {%0,%1,%2,%3}, [%4];"
        : "=r"(r[0]), "=r"(r[1]), "=r"(r[2]), "=r"(r[3]) : "r"(addr));
}

__device__ __forceinline__ void mma16816(float* c, const uint32_t* a, uint32_t b0, uint32_t b1) {
    asm volatile("mma.sync.aligned.m16n8k16.row.col.f32.f16.f16.f32 "
        "{%0,%1,%2,%3}, {%4,%5,%6,%7}, {%8,%9}, {%0,%1,%2,%3};"
        : "+f"(c[0]), "+f"(c[1]), "+f"(c[2]), "+f"(c[3])
        : "r"(a[0]), "r"(a[1]), "r"(a[2]), "r"(a[3]), "r"(b0), "r"(b1));
}

#define CP16(dst, src) \
    asm volatile("cp.async.cg.shared.global [%0], [%1], 16;" :: "r"(dst), "l"(src))
#define CPCOMMIT() asm volatile("cp.async.commit_group;" ::: "memory")
#define CPWAIT1()  asm volatile("cp.async.wait_group 1;"  ::: "memory")

__device__ __forceinline__ void st2(float* p, float x, float y) {
    float2 v; v.x = x; v.y = y; *(float2*)p = v;
}
__device__ __forceinline__ void sth2(__half* p, float x, float y) {
    *(__half2*)p = __floats2half2_rn(x, y);
}
__device__ __forceinline__ void split_st(__half* hp, __half* lp, size_t i, float x, float y) {
    __half2 h = __floats2half2_rn(x, y);
    float lx = x - __half2float(h.x), ly = y - __half2float(h.y);
    *(__half2*)(hp + i) = h;
    *(__half2*)(lp + i) = __floats2half2_rn(lx, ly);
}

// ---------------- unified HMMA GEMM (128x64 tile, cp.async 3-stage) ----------
// D[m][n] = sum_k A[m][k]*B[n][k]. A plain fp16; B split hi/lo iff SPLITB.
// MODE 0 (SPLITB=1): A=hxnt[s][c], B=wq h/l,  K=256  -> q_h / k_h / v_h(transposed) + bias
// MODE 1 (SPLITB=0): A=q_h[s][c],  B=k_h[t][c],K=256 -> attn[s][t]*SCALE (fp32)
// MODE 2 (SPLITB=0): A=p_h[s][t],  B=v_h[c][t],K=1024-> ao h/l [s][c]
// MODE 3 (SPLITB=1): A=woh[o][c],  B=ao h/l,  K=256  -> out[o][s] + bias + resid
#define LDS    40                  // padded fp16 row stride (80B)
#define AELEM  (128 * LDS)         // 5120 halfs
#define BELEM  (64 * LDS)          // 2560 halfs
#define OFF_BH (AELEM * 2)         // 10240 B
#define SMEMB_MAX (3 * ((AELEM + 2 * BELEM) * 2))   // 61440 B (split case)

template <int KTOT, int SPLITB>
__device__ __forceinline__ void stage_chunk(
    const __half* __restrict__ Ap, const __half* __restrict__ Bph,
    const __half* __restrict__ Bpl, uint32_t sbuf, int tid, int k0)
{
#pragma unroll
    for (int s = 0; s < 2; s++) {
        const int slot = tid + s * 256;
        const int row = slot >> 2, seg = slot & 3;
        CP16(sbuf + (uint32_t)((row * LDS + seg * 8) * 2),
             Ap + (size_t)row * KTOT + k0 + seg * 8);
    }
    {
        const int row = tid >> 2, seg = tid & 3;
        const uint32_t d = (uint32_t)((row * LDS + seg * 8) * 2);
        const size_t  g = (size_t)row * KTOT + k0 + seg * 8;
        CP16(sbuf + OFF_BH + d, Bph + g);
        if (SPLITB)
            CP16(sbuf + OFF_BH + (uint32_t)(BELEM * 2) + d, Bpl + g);
    }
}

template <int MODE, int SPLITB>
__global__ void __launch_bounds__(256, 2) mma_gemm(
    const float* __restrict__ bias,
    const float* __restrict__ resid, float* __restrict__ Cout)
{
    constexpr int KTOT = (MODE == 2) ? 1024 : 256;
    constexpr int NCH = KTOT / 32;
    constexpr uint32_t STAGEB = (AELEM + (SPLITB ? 2 : 1) * BELEM) * 2;
    extern __shared__ __half dsm[];

    const int tid = threadIdx.x;
    const int lane = tid & 31, wid = tid >> 5;
    const int bz = blockIdx.z;
    const int bm = blockIdx.y * 128, bn = blockIdx.x * 64;

    const __half *Ah, *Bh, *Bl = nullptr;
    if (MODE == 0) { Ah = g_hxnt + (size_t)bz * HW * CH; Bh = g_wqh; Bl = g_wql; }
    if (MODE == 1) { Ah = g_qh + (size_t)bz * HW * CH;   Bh = g_kh + (size_t)bz * HW * CH; }
    if (MODE == 2) { Ah = g_ph + (size_t)bz * HW * HW;   Bh = g_vh + (size_t)bz * CH * HW; }
    if (MODE == 3) { Ah = g_woh; Bh = g_aoh + (size_t)bz * HW * CH; Bl = g_aol + (size_t)bz * HW * CH; }

    const __half* Ap  = Ah + (size_t)bm * KTOT;
    const __half* Bph = Bh + (size_t)bn * KTOT;
    const __half* Bpl = SPLITB ? (Bl + (size_t)bn * KTOT) : nullptr;

    const int wm = (wid >> 1) * 32, wn = (wid & 1) * 32;

    // ldmatrix base addresses relative to stage 0
    const uint32_t u0 = smem_u32(dsm);
    const int rowA = wm + (lane & 15);
    const int kOffA = (lane >> 4) << 3;
    const int rowB = wn + (lane & 7) + ((lane >> 4) << 3);
    const int kOffB = ((lane >> 3) & 1) << 3;
    uint32_t aHb[2], bHb[2];
#pragma unroll
    for (int mt = 0; mt < 2; mt++)
        aHb[mt] = u0 + (uint32_t)(((rowA + mt * 16) * LDS + kOffA) * 2);
#pragma unroll
    for (int p = 0; p < 2; p++)
        bHb[p] = u0 + (uint32_t)OFF_BH + (uint32_t)(((rowB + p * 16) * LDS + kOffB) * 2);

    float acc[2][4][4] = {};

    // prologue: issue chunks 0 and 1
    stage_chunk<KTOT, SPLITB>(Ap, Bph, Bpl, u0, tid, 0);
    CPCOMMIT();
    stage_chunk<KTOT, SPLITB>(Ap, Bph, Bpl, u0 + STAGEB, tid, 32);
    CPCOMMIT();

    for (int ch = 0; ch < NCH; ch++) {
        CPWAIT1();                 // chunk ch resident
        __syncthreads();
        if (ch + 2 < NCH) {
            const int nb = (ch + 2) % 3;
            stage_chunk<KTOT, SPLITB>(Ap, Bph, Bpl, u0 + nb * STAGEB, tid, (ch + 2) * 32);
        }
        CPCOMMIT();                // uniform commit count

        const uint32_t boff = (uint32_t)((ch % 3) * STAGEB);
#pragma unroll
        for (int ks = 0; ks < 2; ks++) {
            uint32_t ahf[2][4], bhf[2][4], blf[2][4];
#pragma unroll
            for (int mt = 0; mt < 2; mt++)
                ldsm4(ahf[mt], aHb[mt] + boff + ks * 32);
#pragma unroll
            for (int p = 0; p < 2; p++) {
                ldsm4(bhf[p], bHb[p] + boff + ks * 32);
                if (SPLITB)
                    ldsm4(blf[p], bHb[p] + boff + (uint32_t)(BELEM * 2) + ks * 32);
            }
#pragma unroll
            for (int mt = 0; mt < 2; mt++)
#pragma unroll
                for (int p = 0; p < 2; p++)
#pragma unroll
                    for (int h = 0; h < 2; h++) {
                        float* c = acc[mt][p * 2 + h];
                        mma16816(c, ahf[mt], bhf[p][h * 2], bhf[p][h * 2 + 1]);
                        if (SPLITB)
                            mma16816(c, ahf[mt], blf[p][h * 2], blf[p][h * 2 + 1]);
                    }
        }
    }

    // ---------------- epilogue -----------------------------------------------
    const int gid = lane >> 2, qid = (lane & 3) * 2;

    if (MODE == 0) {
#pragma unroll
        for (int mt = 0; mt < 2; mt++) {
            const int s = bm + wm + mt * 16 + gid;
#pragma unroll
            for (int nt = 0; nt < 4; nt++) {
                const int oc = bn + wn + nt * 8 + qid;      // 0..767
                const int third = oc >> 8;
                const int cl = oc & 255;
                const float b0v = bias[oc], b1v = bias[oc + 1];
                float* a = acc[mt][nt];
                const float v0 = a[0] + b0v, v1 = a[1] + b1v;
                const float v2 = a[2] + b0v, v3 = a[3] + b1v;
                if (third == 0) {
                    const size_t i0 = ((size_t)bz * HW + s) * CH + cl;
                    const size_t i1 = ((size_t)bz * HW + s + 8) * CH + cl;
                    sth2(&g_qh[i0], v0, v1);
                    sth2(&g_qh[i1], v2, v3);
                } else if (third == 1) {
                    const size_t i0 = ((size_t)bz * HW + s) * CH + cl;
                    const size_t i1 = ((size_t)bz * HW + s + 8) * CH + cl;
                    sth2(&g_kh[i0], v0, v1);
                    sth2(&g_kh[i1], v2, v3);
                } else {
                    // v written transposed: g_vh[b][c][t], c = cl(+1), t = s(+8)
                    __half* vb = g_vh + (size_t)bz * CH * HW;
                    vb[(size_t)cl * HW + s]           = __float2half_rn(v0);
                    vb[(size_t)(cl + 1) * HW + s]     = __float2half_rn(v1);
                    vb[(size_t)cl * HW + s + 8]       = __float2half_rn(v2);
                    vb[(size_t)(cl + 1) * HW + s + 8] = __float2half_rn(v3);
                }
            }
        }
    }
    if (MODE == 1) {
        float* dst = g_attn + (size_t)bz * HW * HW;
#pragma unroll
        for (int mt = 0; mt < 2; mt++) {
            const int s = bm + wm + mt * 16 + gid;
#pragma unroll
            for (int nt = 0; nt < 4; nt++) {
                const int t = bn + wn + nt * 8 + qid;
                float* a = acc[mt][nt];
                st2(&dst[(size_t)s * HW + t], a[0] * SCALE, a[1] * SCALE);
                st2(&dst[(size_t)(s + 8) * HW + t], a[2] * SCALE, a[3] * SCALE);
            }
        }
    }
    if (MODE == 2) {
#pragma unroll
        for (int mt = 0; mt < 2; mt++) {
            const int s = bm + wm + mt * 16 + gid;
#pragma unroll
            for (int nt = 0; nt < 4; nt++) {
                const int c = bn + wn + nt * 8 + qid;
                float* a = acc[mt][nt];
                const size_t i0 = ((size_t)bz * HW + s) * CH + c;
                const size_t i1 = ((size_t)bz * HW + s + 8) * CH + c;
                split_st(g_aoh, g_aol, i0, a[0], a[1]);
                split_st(g_aoh, g_aol, i1, a[2], a[3]);
            }
        }
    }
    if (MODE == 3) {
#pragma unroll
        for (int mt = 0; mt < 2; mt++) {
            const int o = bm + wm + mt * 16 + gid;
            const float bo0 = bias[o], bo8 = bias[o + 8];
#pragma unroll
            for (int nt = 0; nt < 4; nt++) {
                const int s = bn + wn + nt * 8 + qid;
                float* a = acc[mt][nt];
                size_t i0 = ((size_t)bz * CH + o) * HW + s;
                size_t i1 = ((size_t)bz * CH + o + 8) * HW + s;
                float2 rv0 = *(const float2*)&resid[i0];
                float2 rv1 = *(const float2*)&resid[i1];
                st2(&Cout[i0], a[0] + bo0 + rv0.x, a[1] + bo0 + rv0.y);
                st2(&Cout[i1], a[2] + bo8 + rv1.x, a[3] + bo8 + rv1.y);
            }
        }
    }
}

// ---------------- weight conversion ------------------------------------------
__global__ void convert_w(const float* __restrict__ wqkv, const float* __restrict__ wout)
{
    const int i = blockIdx.x * 256 + threadIdx.x;
    if (i < 3 * CH * CH) {
        float v = wqkv[i];
        __half h = __float2half_rn(v);
        g_wqh[i] = h;
        g_wql[i] = __float2half_rn(v - __half2float(h));
    }
    if (i < CH * CH)
        g_woh[i] = __float2half_rn(wout[i]);
}

// ---------------- GroupNorm (writes x_norm^T [b][s][c] fp16) ------------------
__global__ void gn_kernel(const float* __restrict__ x,
                          const float* __restrict__ wt,
                          const float* __restrict__ bs)
{
    const int bg = blockIdx.x;              // b*8+g
    const int b = bg >> 3, g = bg & 7;
    const size_t base = (size_t)bg * (32 * HW);
    const int t = threadIdx.x;
    const float4* x4 = (const float4*)(x + base);

    float s = 0.f, s2 = 0.f;
#pragma unroll 4
    for (int i = t; i < 32 * HW / 4; i += 256) {
        float4 v = x4[i];
        s += v.x + v.y + v.z + v.w;
        s2 += v.x * v.x + v.y * v.y + v.z * v.z + v.w * v.w;
    }
    __shared__ float rs[256], rq[256];
    rs[t] = s; rq[t] = s2;
    __syncthreads();
    for (int o = 128; o > 0; o >>= 1) {
        if (t < o) { rs[t] += rs[t + o]; rq[t] += rq[t + o]; }
        __syncthreads();
    }
    __shared__ float s_m, s_r;
    if (t == 0) {
        float m = rs[0] * (1.0f / (32.f * HW));
        float v = rq[0] * (1.0f / (32.f * HW)) - m * m;
        s_m = m; s_r = rsqrtf(v + EPSV);
    }
    __syncthreads();
    __shared__ float cw[32], cb[32];
    if (t < 32) {
        float w = wt[g * 32 + t] * s_r;
        cw[t] = w;
        cb[t] = bs[g * 32 + t] - s_m * w;
    }
    __syncthreads();

    __shared__ float sm[32][33];
    const int row = t >> 5, col = t & 31;
    for (int s0 = 0; s0 < HW; s0 += 32) {
#pragma unroll
        for (int cr = 0; cr < 32; cr += 8) {
            int c = cr + row;
            sm[c][col] = x[base + (size_t)c * HW + s0 + col] * cw[c] + cb[c];
        }
        __syncthreads();
#pragma unroll
        for (int sr = 0; sr < 32; sr += 8) {
            int sl = sr + row;
            g_hxnt[((size_t)b * HW + s0 + sl) * CH + g * 32 + col] =
                __float2half_rn(sm[col][sl]);
        }
        __syncthreads();
    }
}

// ---------------- softmax (fp32 scores -> fp16 probs) -------------------------
__global__ void softmax_kernel()
{
    const float* row = g_attn + (size_t)blockIdx.x * HW;
    __half* orow = g_ph + (size_t)blockIdx.x * HW;
    const int t = threadIdx.x;
    float4 v = ((const float4*)row)[t];

    float m = fmaxf(fmaxf(v.x, v.y), fmaxf(v.z, v.w));
#pragma unroll
    for (int o = 16; o > 0; o >>= 1) m = fmaxf(m, __shfl_xor_sync(0xffffffffu, m, o));
    __shared__ float red[8];
    if ((t & 31) == 0) red[t >> 5] = m;
    __syncthreads();
    float mm = red[0];
#pragma unroll
    for (int i = 1; i < 8; i++) mm = fmaxf(mm, red[i]);
    __syncthreads();

    float e0 = __expf(v.x - mm), e1 = __expf(v.y - mm);
    float e2 = __expf(v.z - mm), e3 = __expf(v.w - mm);
    float s = e0 + e1 + e2 + e3;
#pragma unroll
    for (int o = 16; o > 0; o >>= 1) s += __shfl_xor_sync(0xffffffffu, s, o);
    if ((t & 31) == 0) red[t >> 5] = s;
    __syncthreads();
    float tot = 0.f;
#pragma unroll
    for (int i = 0; i < 8; i++) tot += red[i];
    float inv = 1.0f / tot;

    uint2 pk;
    __half2 p01 = __floats2half2_rn(e0 * inv, e1 * inv);
    __half2 p23 = __floats2half2_rn(e2 * inv, e3 * inv);
    pk.x = *(uint32_t*)&p01; pk.y = *(uint32_t*)&p23;
    *(uint2*)(orow + t * 4) = pk;
}

// ---------------- launch -------------------------------------------------------
extern "C" void kernel_launch(void* const* d_in, const int* in_sizes, int n_in,
                              void* d_out, int out_size)
{
    const float* x    = (const float*)d_in[0];
    const float* gnw  = (const float*)d_in[1];
    const float* gnb  = (const float*)d_in[2];
    const float* wqkv = (const float*)d_in[3];
    const float* bqkv = (const float*)d_in[4];
    const float* wout = (const float*)d_in[5];
    const float* bout = (const float*)d_in[6];
    float* out = (float*)d_out;

    cudaFuncSetAttribute(mma_gemm<0,1>, cudaFuncAttributeMaxDynamicSharedMemorySize, SMEMB_MAX);
    cudaFuncSetAttribute(mma_gemm<1,0>, cudaFuncAttributeMaxDynamicSharedMemorySize, SMEMB_MAX);
    cudaFuncSetAttribute(mma_gemm<2,0>, cudaFuncAttributeMaxDynamicSharedMemorySize, SMEMB_MAX);
    cudaFuncSetAttribute(mma_gemm<3,1>, cudaFuncAttributeMaxDynamicSharedMemorySize, SMEMB_MAX);

    const uint32_t smem_split = 3 * ((AELEM + 2 * BELEM) * 2);
    const uint32_t smem_plain = 3 * ((AELEM + BELEM) * 2);

    convert_w<<<(3 * CH * CH + 255) / 256, 256>>>(wqkv, wout);
    gn_kernel<<<BATCH * 8, 256>>>(x, gnw, gnb);
    mma_gemm<0,1><<<dim3(12, 8, BATCH), 256, smem_split>>>(bqkv, nullptr, nullptr);
    mma_gemm<1,0><<<dim3(16, 8, BATCH), 256, smem_plain>>>(nullptr, nullptr, nullptr);
    softmax_kernel<<<BATCH * HW, 256>>>();
    mma_gemm<2,0><<<dim3(4, 8, BATCH), 256, smem_plain>>>(nullptr, nullptr, nullptr);
    mma_gemm<3,1><<<dim3(16, 2, BATCH), 256, smem_split>>>(bout, x, out);
}

// round 9
// speedup vs baseline: 5.6246x; 1.0602x over previous
#include <cuda_runtime.h>
#include <cuda_fp16.h>
#include <cstdint>

#define BATCH 32
#define CH    256
#define HW    1024
#define EPSV  1e-5f
#define SCALE 0.0625f

// ---------------- scratch (device globals; no allocation allowed) ----------
__device__ __align__(256) __half  g_hxnt[(size_t)BATCH * HW * CH];  // [b][s][c]
__device__ __align__(256) __half  g_qh  [(size_t)BATCH * HW * CH];  // [b][s][c]
__device__ __align__(256) __half  g_kh  [(size_t)BATCH * HW * CH];  // [b][t][c]
__device__ __align__(256) __half  g_vh  [(size_t)BATCH * CH * HW];  // [b][c][t]
__device__ __align__(256) float   g_attn[(size_t)BATCH * HW * HW];  // fp32 scores
__device__ __align__(256) __half  g_ph  [(size_t)BATCH * HW * HW];  // fp16 probs
__device__ __align__(256) __half  g_aoh [(size_t)BATCH * HW * CH];  // [b][s][c]
__device__ __align__(256) __half  g_aol [(size_t)BATCH * HW * CH];
__device__ __align__(256) __half  g_wqh [3 * CH * CH];
__device__ __align__(256) __half  g_wql [3 * CH * CH];
__device__ __align__(256) __half  g_woh [CH * CH];

// ---------------- helpers ----------------------------------------------------
__device__ __forceinline__ uint32_t smem_u32(const void* p) {
    uint32_t a;
    asm("{ .reg .u64 t; cvta.to.shared.u64 t, %1; cvt.u32.u64 %0, t; }" : "=r"(a) : "l"(p));
    return a;
}

__device__ __forceinline__ void ldsm4(uint32_t* r, uint32_t addr) {
    asm volatile("ldmatrix.sync.aligned.m8n8.x4.shared.b16 {%0,%1,%2,%3}, [%4];"
        : "=r"(r[0]), "=r"(r[1]), "=r"(r[2]), "=r"(r[3]) : "r"(addr));
}

__device__ __forceinline__ void mma16816(float* c, const uint32_t* a, uint32_t b0, uint32_t b1) {
    asm volatile("mma.sync.aligned.m16n8k16.row.col.f32.f16.f16.f32 "
        "{%0,%1,%2,%3}, {%4,%5,%6,%7}, {%8,%9}, {%0,%1,%2,%3};"
        : "+f"(c[0]), "+f"(c[1]), "+f"(c[2]), "+f"(c[3])
        : "r"(a[0]), "r"(a[1]), "r"(a[2]), "r"(a[3]), "r"(b0), "r"(b1));
}

#define CP16(dst, src) \
    asm volatile("cp.async.cg.shared.global [%0], [%1], 16;" :: "r"(dst), "l"(src))
#define CPCOMMIT() asm volatile("cp.async.commit_group;" ::: "memory")
#define CPWAIT1()  asm volatile("cp.async.wait_group 1;"  ::: "memory")

__device__ __forceinline__ void st2(float* p, float x, float y) {
    float2 v; v.x = x; v.y = y; *(float2*)p = v;
}
__device__ __forceinline__ void sth2(__half* p, float x, float y) {
    *(__half2*)p = __floats2half2_rn(x, y);
}
__device__ __forceinline__ void split_st(__half* hp, __half* lp, size_t i, float x, float y) {
    __half2 h = __floats2half2_rn(x, y);
    float lx = x - __half2float(h.x), ly = y - __half2float(h.y);
    *(__half2*)(hp + i) = h;
    *(__half2*)(lp + i) = __floats2half2_rn(lx, ly);
}

// ---------------- unified HMMA GEMM (128x64 tile, K-chunk 64, 3-stage) -------
// D[m][n] = sum_k A[m][k]*B[n][k]. A plain fp16; B split hi/lo iff SPLITB.
// MODE 0 (SPLITB=1): A=hxnt[s][c], B=wq h/l,  K=256  -> q_h / k_h / v_h(transposed) + bias
// MODE 1 (SPLITB=0): A=q_h[s][c],  B=k_h[t][c],K=256 -> attn[s][t]*SCALE (fp32)
// MODE 2 (SPLITB=0): A=p_h[s][t],  B=v_h[c][t],K=1024-> ao h/l [s][c]
// MODE 3 (SPLITB=1): A=woh[o][c],  B=ao h/l,  K=256  -> out[o][s] + bias + resid
#define KC     64                  // K per chunk
#define LDS    72                  // padded fp16 row stride (144B)
#define AELEM  (128 * LDS)         // 9216 halfs
#define BELEM  (64 * LDS)          // 4608 halfs
#define OFF_BH (AELEM * 2)         // 18432 B
#define STG_PLAIN ((AELEM + BELEM) * 2)       // 27648 B
#define STG_SPLIT ((AELEM + 2 * BELEM) * 2)   // 36864 B

template <int KTOT, int SPLITB>
__device__ __forceinline__ void stage_chunk(
    const __half* __restrict__ Ap, const __half* __restrict__ Bph,
    const __half* __restrict__ Bpl, uint32_t sbuf, int tid, int k0)
{
#pragma unroll
    for (int s = 0; s < 4; s++) {                       // A: 128 rows x 8 segs
        const int slot = tid + s * 256;
        const int row = slot >> 3, seg = slot & 7;
        CP16(sbuf + (uint32_t)((row * LDS + seg * 8) * 2),
             Ap + (size_t)row * KTOT + k0 + seg * 8);
    }
#pragma unroll
    for (int s = 0; s < 2; s++) {                       // B: 64 rows x 8 segs
        const int slot = tid + s * 256;
        const int row = slot >> 3, seg = slot & 7;
        const uint32_t d = (uint32_t)((row * LDS + seg * 8) * 2);
        const size_t  g = (size_t)row * KTOT + k0 + seg * 8;
        CP16(sbuf + OFF_BH + d, Bph + g);
        if (SPLITB)
            CP16(sbuf + OFF_BH + (uint32_t)(BELEM * 2) + d, Bpl + g);
    }
}

template <int MODE, int SPLITB>
__global__ void __launch_bounds__(256, 2) mma_gemm(
    const float* __restrict__ bias,
    const float* __restrict__ resid, float* __restrict__ Cout)
{
    constexpr int KTOT = (MODE == 2) ? 1024 : 256;
    constexpr int NCH = KTOT / KC;
    constexpr uint32_t STAGEB = SPLITB ? STG_SPLIT : STG_PLAIN;
    extern __shared__ __half dsm[];

    const int tid = threadIdx.x;
    const int lane = tid & 31, wid = tid >> 5;
    const int bz = blockIdx.z;
    const int bm = blockIdx.y * 128, bn = blockIdx.x * 64;

    const __half *Ah, *Bh, *Bl = nullptr;
    if (MODE == 0) { Ah = g_hxnt + (size_t)bz * HW * CH; Bh = g_wqh; Bl = g_wql; }
    if (MODE == 1) { Ah = g_qh + (size_t)bz * HW * CH;   Bh = g_kh + (size_t)bz * HW * CH; }
    if (MODE == 2) { Ah = g_ph + (size_t)bz * HW * HW;   Bh = g_vh + (size_t)bz * CH * HW; }
    if (MODE == 3) { Ah = g_woh; Bh = g_aoh + (size_t)bz * HW * CH; Bl = g_aol + (size_t)bz * HW * CH; }

    const __half* Ap  = Ah + (size_t)bm * KTOT;
    const __half* Bph = Bh + (size_t)bn * KTOT;
    const __half* Bpl = SPLITB ? (Bl + (size_t)bn * KTOT) : nullptr;

    const int wm = (wid >> 1) * 32, wn = (wid & 1) * 32;

    // ldmatrix base addresses relative to stage 0
    const uint32_t u0 = smem_u32(dsm);
    const int rowA = wm + (lane & 15);
    const int kOffA = (lane >> 4) << 3;
    const int rowB = wn + (lane & 7) + ((lane >> 4) << 3);
    const int kOffB = ((lane >> 3) & 1) << 3;
    uint32_t aHb[2], bHb[2];
#pragma unroll
    for (int mt = 0; mt < 2; mt++)
        aHb[mt] = u0 + (uint32_t)(((rowA + mt * 16) * LDS + kOffA) * 2);
#pragma unroll
    for (int p = 0; p < 2; p++)
        bHb[p] = u0 + (uint32_t)OFF_BH + (uint32_t)(((rowB + p * 16) * LDS + kOffB) * 2);

    float acc[2][4][4] = {};

    // prologue: issue chunks 0 and 1
    stage_chunk<KTOT, SPLITB>(Ap, Bph, Bpl, u0, tid, 0);
    CPCOMMIT();
    stage_chunk<KTOT, SPLITB>(Ap, Bph, Bpl, u0 + STAGEB, tid, KC);
    CPCOMMIT();

    for (int ch = 0; ch < NCH; ch++) {
        CPWAIT1();                 // chunk ch resident
        __syncthreads();
        if (ch + 2 < NCH) {
            const int nb = (ch + 2) % 3;
            stage_chunk<KTOT, SPLITB>(Ap, Bph, Bpl, u0 + nb * STAGEB, tid, (ch + 2) * KC);
        }
        CPCOMMIT();                // uniform commit count

        const uint32_t boff = (uint32_t)((ch % 3) * STAGEB);
#pragma unroll
        for (int ks = 0; ks < 4; ks++) {
            uint32_t ahf[2][4], bhf[2][4], blf[2][4];
#pragma unroll
            for (int mt = 0; mt < 2; mt++)
                ldsm4(ahf[mt], aHb[mt] + boff + ks * 32);
#pragma unroll
            for (int p = 0; p < 2; p++) {
                ldsm4(bhf[p], bHb[p] + boff + ks * 32);
                if (SPLITB)
                    ldsm4(blf[p], bHb[p] + boff + (uint32_t)(BELEM * 2) + ks * 32);
            }
#pragma unroll
            for (int mt = 0; mt < 2; mt++)
#pragma unroll
                for (int p = 0; p < 2; p++)
#pragma unroll
                    for (int h = 0; h < 2; h++) {
                        float* c = acc[mt][p * 2 + h];
                        mma16816(c, ahf[mt], bhf[p][h * 2], bhf[p][h * 2 + 1]);
                        if (SPLITB)
                            mma16816(c, ahf[mt], blf[p][h * 2], blf[p][h * 2 + 1]);
                    }
        }
    }

    // ---------------- epilogue -----------------------------------------------
    const int gid = lane >> 2, qid = (lane & 3) * 2;

    if (MODE == 0) {
#pragma unroll
        for (int mt = 0; mt < 2; mt++) {
            const int s = bm + wm + mt * 16 + gid;
#pragma unroll
            for (int nt = 0; nt < 4; nt++) {
                const int oc = bn + wn + nt * 8 + qid;      // 0..767
                const int third = oc >> 8;
                const int cl = oc & 255;
                const float b0v = bias[oc], b1v = bias[oc + 1];
                float* a = acc[mt][nt];
                const float v0 = a[0] + b0v, v1 = a[1] + b1v;
                const float v2 = a[2] + b0v, v3 = a[3] + b1v;
                if (third == 0) {
                    const size_t i0 = ((size_t)bz * HW + s) * CH + cl;
                    const size_t i1 = ((size_t)bz * HW + s + 8) * CH + cl;
                    sth2(&g_qh[i0], v0, v1);
                    sth2(&g_qh[i1], v2, v3);
                } else if (third == 1) {
                    const size_t i0 = ((size_t)bz * HW + s) * CH + cl;
                    const size_t i1 = ((size_t)bz * HW + s + 8) * CH + cl;
                    sth2(&g_kh[i0], v0, v1);
                    sth2(&g_kh[i1], v2, v3);
                } else {
                    __half* vb = g_vh + (size_t)bz * CH * HW;
                    vb[(size_t)cl * HW + s]           = __float2half_rn(v0);
                    vb[(size_t)(cl + 1) * HW + s]     = __float2half_rn(v1);
                    vb[(size_t)cl * HW + s + 8]       = __float2half_rn(v2);
                    vb[(size_t)(cl + 1) * HW + s + 8] = __float2half_rn(v3);
                }
            }
        }
    }
    if (MODE == 1) {
        float* dst = g_attn + (size_t)bz * HW * HW;
#pragma unroll
        for (int mt = 0; mt < 2; mt++) {
            const int s = bm + wm + mt * 16 + gid;
#pragma unroll
            for (int nt = 0; nt < 4; nt++) {
                const int t = bn + wn + nt * 8 + qid;
                float* a = acc[mt][nt];
                st2(&dst[(size_t)s * HW + t], a[0] * SCALE, a[1] * SCALE);
                st2(&dst[(size_t)(s + 8) * HW + t], a[2] * SCALE, a[3] * SCALE);
            }
        }
    }
    if (MODE == 2) {
#pragma unroll
        for (int mt = 0; mt < 2; mt++) {
            const int s = bm + wm + mt * 16 + gid;
#pragma unroll
            for (int nt = 0; nt < 4; nt++) {
                const int c = bn + wn + nt * 8 + qid;
                float* a = acc[mt][nt];
                const size_t i0 = ((size_t)bz * HW + s) * CH + c;
                const size_t i1 = ((size_t)bz * HW + s + 8) * CH + c;
                split_st(g_aoh, g_aol, i0, a[0], a[1]);
                split_st(g_aoh, g_aol, i1, a[2], a[3]);
            }
        }
    }
    if (MODE == 3) {
#pragma unroll
        for (int mt = 0; mt < 2; mt++) {
            const int o = bm + wm + mt * 16 + gid;
            const float bo0 = bias[o], bo8 = bias[o + 8];
#pragma unroll
            for (int nt = 0; nt < 4; nt++) {
                const int s = bn + wn + nt * 8 + qid;
                float* a = acc[mt][nt];
                size_t i0 = ((size_t)bz * CH + o) * HW + s;
                size_t i1 = ((size_t)bz * CH + o + 8) * HW + s;
                float2 rv0 = *(const float2*)&resid[i0];
                float2 rv1 = *(const float2*)&resid[i1];
                st2(&Cout[i0], a[0] + bo0 + rv0.x, a[1] + bo0 + rv0.y);
                st2(&Cout[i1], a[2] + bo8 + rv1.x, a[3] + bo8 + rv1.y);
            }
        }
    }
}

// ---------------- weight conversion ------------------------------------------
__global__ void convert_w(const float* __restrict__ wqkv, const float* __restrict__ wout)
{
    const int i = blockIdx.x * 256 + threadIdx.x;
    if (i < 3 * CH * CH) {
        float v = wqkv[i];
        __half h = __float2half_rn(v);
        g_wqh[i] = h;
        g_wql[i] = __float2half_rn(v - __half2float(h));
    }
    if (i < CH * CH)
        g_woh[i] = __float2half_rn(wout[i]);
}

// ---------------- GroupNorm (writes x_norm^T [b][s][c] fp16) ------------------
__global__ void gn_kernel(const float* __restrict__ x,
                          const float* __restrict__ wt,
                          const float* __restrict__ bs)
{
    const int bg = blockIdx.x;              // b*8+g
    const int b = bg >> 3, g = bg & 7;
    const size_t base = (size_t)bg * (32 * HW);
    const int t = threadIdx.x;
    const float4* x4 = (const float4*)(x + base);

    float s = 0.f, s2 = 0.f;
#pragma unroll 4
    for (int i = t; i < 32 * HW / 4; i += 256) {
        float4 v = x4[i];
        s += v.x + v.y + v.z + v.w;
        s2 += v.x * v.x + v.y * v.y + v.z * v.z + v.w * v.w;
    }
    __shared__ float rs[256], rq[256];
    rs[t] = s; rq[t] = s2;
    __syncthreads();
    for (int o = 128; o > 0; o >>= 1) {
        if (t < o) { rs[t] += rs[t + o]; rq[t] += rq[t + o]; }
        __syncthreads();
    }
    __shared__ float s_m, s_r;
    if (t == 0) {
        float m = rs[0] * (1.0f / (32.f * HW));
        float v = rq[0] * (1.0f / (32.f * HW)) - m * m;
        s_m = m; s_r = rsqrtf(v + EPSV);
    }
    __syncthreads();
    __shared__ float cw[32], cb[32];
    if (t < 32) {
        float w = wt[g * 32 + t] * s_r;
        cw[t] = w;
        cb[t] = bs[g * 32 + t] - s_m * w;
    }
    __syncthreads();

    __shared__ float sm[32][33];
    const int row = t >> 5, col = t & 31;
    for (int s0 = 0; s0 < HW; s0 += 32) {
#pragma unroll
        for (int cr = 0; cr < 32; cr += 8) {
            int c = cr + row;
            sm[c][col] = x[base + (size_t)c * HW + s0 + col] * cw[c] + cb[c];
        }
        __syncthreads();
#pragma unroll
        for (int sr = 0; sr < 32; sr += 8) {
            int sl = sr + row;
            g_hxnt[((size_t)b * HW + s0 + sl) * CH + g * 32 + col] =
                __float2half_rn(sm[col][sl]);
        }
        __syncthreads();
    }
}

// ---------------- softmax (fp32 scores -> fp16 probs) -------------------------
__global__ void softmax_kernel()
{
    const float* row = g_attn + (size_t)blockIdx.x * HW;
    __half* orow = g_ph + (size_t)blockIdx.x * HW;
    const int t = threadIdx.x;
    float4 v = ((const float4*)row)[t];

    float m = fmaxf(fmaxf(v.x, v.y), fmaxf(v.z, v.w));
#pragma unroll
    for (int o = 16; o > 0; o >>= 1) m = fmaxf(m, __shfl_xor_sync(0xffffffffu, m, o));
    __shared__ float red[8];
    if ((t & 31) == 0) red[t >> 5] = m;
    __syncthreads();
    float mm = red[0];
#pragma unroll
    for (int i = 1; i < 8; i++) mm = fmaxf(mm, red[i]);
    __syncthreads();

    float e0 = __expf(v.x - mm), e1 = __expf(v.y - mm);
    float e2 = __expf(v.z - mm), e3 = __expf(v.w - mm);
    float s = e0 + e1 + e2 + e3;
#pragma unroll
    for (int o = 16; o > 0; o >>= 1) s += __shfl_xor_sync(0xffffffffu, s, o);
    if ((t & 31) == 0) red[t >> 5] = s;
    __syncthreads();
    float tot = 0.f;
#pragma unroll
    for (int i = 0; i < 8; i++) tot += red[i];
    float inv = 1.0f / tot;

    uint2 pk;
    __half2 p01 = __floats2half2_rn(e0 * inv, e1 * inv);
    __half2 p23 = __floats2half2_rn(e2 * inv, e3 * inv);
    pk.x = *(uint32_t*)&p01; pk.y = *(uint32_t*)&p23;
    *(uint2*)(orow + t * 4) = pk;
}

// ---------------- launch -------------------------------------------------------
extern "C" void kernel_launch(void* const* d_in, const int* in_sizes, int n_in,
                              void* d_out, int out_size)
{
    const float* x    = (const float*)d_in[0];
    const float* gnw  = (const float*)d_in[1];
    const float* gnb  = (const float*)d_in[2];
    const float* wqkv = (const float*)d_in[3];
    const float* bqkv = (const float*)d_in[4];
    const float* wout = (const float*)d_in[5];
    const float* bout = (const float*)d_in[6];
    float* out = (float*)d_out;

    const uint32_t smem_split = 3 * STG_SPLIT;   // 110592
    const uint32_t smem_plain = 3 * STG_PLAIN;   // 82944

    cudaFuncSetAttribute(mma_gemm<0,1>, cudaFuncAttributeMaxDynamicSharedMemorySize, smem_split);
    cudaFuncSetAttribute(mma_gemm<1,0>, cudaFuncAttributeMaxDynamicSharedMemorySize, smem_plain);
    cudaFuncSetAttribute(mma_gemm<2,0>, cudaFuncAttributeMaxDynamicSharedMemorySize, smem_plain);
    cudaFuncSetAttribute(mma_gemm<3,1>, cudaFuncAttributeMaxDynamicSharedMemorySize, smem_split);

    convert_w<<<(3 * CH * CH + 255) / 256, 256>>>(wqkv, wout);
    gn_kernel<<<BATCH * 8, 256>>>(x, gnw, gnb);
    mma_gemm<0,1><<<dim3(12, 8, BATCH), 256, smem_split>>>(bqkv, nullptr, nullptr);
    mma_gemm<1,0><<<dim3(16, 8, BATCH), 256, smem_plain>>>(nullptr, nullptr, nullptr);
    softmax_kernel<<<BATCH * HW, 256>>>();
    mma_gemm<2,0><<<dim3(4, 8, BATCH), 256, smem_plain>>>(nullptr, nullptr, nullptr);
    mma_gemm<3,1><<<dim3(16, 2, BATCH), 256, smem_split>>>(bout, x, out);
}

// round 10
// speedup vs baseline: 5.9640x; 1.0603x over previous
#include <cuda_runtime.h>
#include <cuda_fp16.h>
#include <cstdint>

#define BATCH 32
#define CH    256
#define HW    1024
#define EPSV  1e-5f
#define SCALE 0.0625f

// ---------------- scratch (device globals; no allocation allowed) ----------
__device__ __align__(256) __half  g_hxnt[(size_t)BATCH * HW * CH];  // [b][s][c]
__device__ __align__(256) __half  g_qh  [(size_t)BATCH * HW * CH];  // [b][s][c]
__device__ __align__(256) __half  g_kh  [(size_t)BATCH * HW * CH];  // [b][t][c]
__device__ __align__(256) __half  g_vh  [(size_t)BATCH * CH * HW];  // [b][c][t]
__device__ __align__(256) float   g_attn[(size_t)BATCH * HW * HW];  // fp32 scores
__device__ __align__(256) __half  g_ph  [(size_t)BATCH * HW * HW];  // fp16 probs
__device__ __align__(256) __half  g_aoh [(size_t)BATCH * HW * CH];  // [b][s][c]
__device__ __align__(256) __half  g_aol [(size_t)BATCH * HW * CH];
__device__ __align__(256) __half  g_wqh [3 * CH * CH];
__device__ __align__(256) __half  g_wql [3 * CH * CH];
__device__ __align__(256) __half  g_woh [CH * CH];

// ---------------- helpers ----------------------------------------------------
__device__ __forceinline__ uint32_t smem_u32(const void* p) {
    uint32_t a;
    asm("{ .reg .u64 t; cvta.to.shared.u64 t, %1; cvt.u32.u64 %0, t; }" : "=r"(a) : "l"(p));
    return a;
}

__device__ __forceinline__ void ldsm4(uint32_t* r, uint32_t addr) {
    asm volatile("ldmatrix.sync.aligned.m8n8.x4.shared.b16 {%0,%1,%2,%3}, [%4];"
        : "=r"(r[0]), "=r"(r[1]), "=r"(r[2]), "=r"(r[3]) : "r"(addr));
}

__device__ __forceinline__ void mma16816(float* c, const uint32_t* a, uint32_t b0, uint32_t b1) {
    asm volatile("mma.sync.aligned.m16n8k16.row.col.f32.f16.f16.f32 "
        "{%0,%1,%2,%3}, {%4,%5,%6,%7}, {%8,%9}, {%0,%1,%2,%3};"
        : "+f"(c[0]), "+f"(c[1]), "+f"(c[2]), "+f"(c[3])
        : "r"(a[0]), "r"(a[1]), "r"(a[2]), "r"(a[3]), "r"(b0), "r"(b1));
}

#define CP16(dst, src) \
    asm volatile("cp.async.cg.shared.global [%0], [%1], 16;" :: "r"(dst), "l"(src))
#define CPCOMMIT() asm volatile("cp.async.commit_group;" ::: "memory")
#define CPWAIT1()  asm volatile("cp.async.wait_group 1;"  ::: "memory")

__device__ __forceinline__ void st2(float* p, float x, float y) {
    float2 v; v.x = x; v.y = y; *(float2*)p = v;
}
__device__ __forceinline__ void sth2(__half* p, float x, float y) {
    *(__half2*)p = __floats2half2_rn(x, y);
}
__device__ __forceinline__ void split_st(__half* hp, __half* lp, size_t i, float x, float y) {
    __half2 h = __floats2half2_rn(x, y);
    float lx = x - __half2float(h.x), ly = y - __half2float(h.y);
    *(__half2*)(hp + i) = h;
    *(__half2*)(lp + i) = __floats2half2_rn(lx, ly);
}

// ---------------- unified HMMA GEMM (128xNT tile, K-chunk 64, 3-stage) -------
// D[m][n] = sum_k A[m][k]*B[n][k]. A plain fp16; B split hi/lo iff SPLITB.
// MODE 0 (SPLITB=1,NT=64) : A=hxnt[s][c], B=wq h/l   -> q_h/k_h/v_h(transposed) + bias
// MODE 1 (SPLITB=0,NT=128): A=q_h[s][c],  B=k_h[t][c]-> attn[s][t]*SCALE (fp32)
// MODE 2 (SPLITB=0,NT=128): A=p_h[s][t],  B=v_h[c][t]-> ao h/l [s][c]
// MODE 3 (SPLITB=1,NT=64) : A=woh[o][c],  B=ao h/l   -> out[o][s] + bias + resid
#define KC     64                  // K per chunk
#define LDS    72                  // padded fp16 row stride (144B)
#define AELEM  (128 * LDS)         // 9216 halfs
#define OFF_BH (AELEM * 2)         // 18432 B

template <int KTOT, int SPLITB, int NT>
__device__ __forceinline__ void stage_chunk(
    const __half* __restrict__ Ap, const __half* __restrict__ Bph,
    const __half* __restrict__ Bpl, uint32_t sbuf, int tid, int k0)
{
#pragma unroll
    for (int s = 0; s < 4; s++) {                       // A: 128 rows x 8 segs
        const int slot = tid + s * 256;
        const int row = slot >> 3, seg = slot & 7;
        CP16(sbuf + (uint32_t)((row * LDS + seg * 8) * 2),
             Ap + (size_t)row * KTOT + k0 + seg * 8);
    }
#pragma unroll
    for (int s = 0; s < NT / 32; s++) {                 // B: NT rows x 8 segs
        const int slot = tid + s * 256;
        const int row = slot >> 3, seg = slot & 7;
        const uint32_t d = (uint32_t)((row * LDS + seg * 8) * 2);
        const size_t  g = (size_t)row * KTOT + k0 + seg * 8;
        CP16(sbuf + OFF_BH + d, Bph + g);
        if (SPLITB)
            CP16(sbuf + OFF_BH + (uint32_t)(NT * LDS * 2) + d, Bpl + g);
    }
}

template <int MODE, int SPLITB, int NT>
__global__ void __launch_bounds__(256, 2) mma_gemm(
    const float* __restrict__ bias,
    const float* __restrict__ resid, float* __restrict__ Cout)
{
    constexpr int KTOT = (MODE == 2) ? 1024 : 256;
    constexpr int NCH = KTOT / KC;
    constexpr int NP = NT / 32;                          // B ldsm tiles per ks
    constexpr uint32_t STAGEB = (AELEM + (SPLITB ? 2 : 1) * NT * LDS) * 2;
    extern __shared__ __half dsm[];

    const int tid = threadIdx.x;
    const int lane = tid & 31, wid = tid >> 5;
    const int bz = blockIdx.z;
    const int bm = blockIdx.y * 128, bn = blockIdx.x * NT;

    const __half *Ah, *Bh, *Bl = nullptr;
    if (MODE == 0) { Ah = g_hxnt + (size_t)bz * HW * CH; Bh = g_wqh; Bl = g_wql; }
    if (MODE == 1) { Ah = g_qh + (size_t)bz * HW * CH;   Bh = g_kh + (size_t)bz * HW * CH; }
    if (MODE == 2) { Ah = g_ph + (size_t)bz * HW * HW;   Bh = g_vh + (size_t)bz * CH * HW; }
    if (MODE == 3) { Ah = g_woh; Bh = g_aoh + (size_t)bz * HW * CH; Bl = g_aol + (size_t)bz * HW * CH; }

    const __half* Ap  = Ah + (size_t)bm * KTOT;
    const __half* Bph = Bh + (size_t)bn * KTOT;
    const __half* Bpl = SPLITB ? (Bl + (size_t)bn * KTOT) : nullptr;

    const int wm = (wid >> 1) * 32, wn = (wid & 1) * (NT / 2);

    // ldmatrix base addresses relative to stage 0
    const uint32_t u0 = smem_u32(dsm);
    const int rowA = wm + (lane & 15);
    const int kOffA = (lane >> 4) << 3;
    const int rowB = wn + (lane & 7) + ((lane >> 4) << 3);
    const int kOffB = ((lane >> 3) & 1) << 3;
    uint32_t aHb[2], bHb[NP];
#pragma unroll
    for (int mt = 0; mt < 2; mt++)
        aHb[mt] = u0 + (uint32_t)(((rowA + mt * 16) * LDS + kOffA) * 2);
#pragma unroll
    for (int p = 0; p < NP; p++)
        bHb[p] = u0 + (uint32_t)OFF_BH + (uint32_t)(((rowB + p * 16) * LDS + kOffB) * 2);

    float acc[2][2 * NP][4] = {};

    // prologue: issue chunks 0 and 1
    stage_chunk<KTOT, SPLITB, NT>(Ap, Bph, Bpl, u0, tid, 0);
    CPCOMMIT();
    stage_chunk<KTOT, SPLITB, NT>(Ap, Bph, Bpl, u0 + STAGEB, tid, KC);
    CPCOMMIT();

    for (int ch = 0; ch < NCH; ch++) {
        CPWAIT1();                 // chunk ch resident
        __syncthreads();
        if (ch + 2 < NCH) {
            const int nb = (ch + 2) % 3;
            stage_chunk<KTOT, SPLITB, NT>(Ap, Bph, Bpl, u0 + nb * STAGEB, tid, (ch + 2) * KC);
        }
        CPCOMMIT();                // uniform commit count

        const uint32_t boff = (uint32_t)((ch % 3) * STAGEB);
#pragma unroll
        for (int ks = 0; ks < 4; ks++) {
            uint32_t ahf[2][4];
#pragma unroll
            for (int mt = 0; mt < 2; mt++)
                ldsm4(ahf[mt], aHb[mt] + boff + ks * 32);
#pragma unroll
            for (int p = 0; p < NP; p++) {
                uint32_t bhf[4];
                ldsm4(bhf, bHb[p] + boff + ks * 32);
#pragma unroll
                for (int mt = 0; mt < 2; mt++)
#pragma unroll
                    for (int h = 0; h < 2; h++)
                        mma16816(acc[mt][p * 2 + h], ahf[mt], bhf[h * 2], bhf[h * 2 + 1]);
                if (SPLITB) {
                    uint32_t blf[4];
                    ldsm4(blf, bHb[p] + boff + (uint32_t)(NT * LDS * 2) + ks * 32);
#pragma unroll
                    for (int mt = 0; mt < 2; mt++)
#pragma unroll
                        for (int h = 0; h < 2; h++)
                            mma16816(acc[mt][p * 2 + h], ahf[mt], blf[h * 2], blf[h * 2 + 1]);
                }
            }
        }
    }

    // ---------------- epilogue -----------------------------------------------
    const int gid = lane >> 2, qid = (lane & 3) * 2;

    if (MODE == 0) {
#pragma unroll
        for (int mt = 0; mt < 2; mt++) {
            const int s = bm + wm + mt * 16 + gid;
#pragma unroll
            for (int nt = 0; nt < 2 * NP; nt++) {
                const int oc = bn + wn + nt * 8 + qid;      // 0..767
                const int third = oc >> 8;
                const int cl = oc & 255;
                const float b0v = bias[oc], b1v = bias[oc + 1];
                float* a = acc[mt][nt];
                const float v0 = a[0] + b0v, v1 = a[1] + b1v;
                const float v2 = a[2] + b0v, v3 = a[3] + b1v;
                if (third == 0) {
                    const size_t i0 = ((size_t)bz * HW + s) * CH + cl;
                    const size_t i1 = ((size_t)bz * HW + s + 8) * CH + cl;
                    sth2(&g_qh[i0], v0, v1);
                    sth2(&g_qh[i1], v2, v3);
                } else if (third == 1) {
                    const size_t i0 = ((size_t)bz * HW + s) * CH + cl;
                    const size_t i1 = ((size_t)bz * HW + s + 8) * CH + cl;
                    sth2(&g_kh[i0], v0, v1);
                    sth2(&g_kh[i1], v2, v3);
                } else {
                    __half* vb = g_vh + (size_t)bz * CH * HW;
                    vb[(size_t)cl * HW + s]           = __float2half_rn(v0);
                    vb[(size_t)(cl + 1) * HW + s]     = __float2half_rn(v1);
                    vb[(size_t)cl * HW + s + 8]       = __float2half_rn(v2);
                    vb[(size_t)(cl + 1) * HW + s + 8] = __float2half_rn(v3);
                }
            }
        }
    }
    if (MODE == 1) {
        float* dst = g_attn + (size_t)bz * HW * HW;
#pragma unroll
        for (int mt = 0; mt < 2; mt++) {
            const int s = bm + wm + mt * 16 + gid;
#pragma unroll
            for (int nt = 0; nt < 2 * NP; nt++) {
                const int t = bn + wn + nt * 8 + qid;
                float* a = acc[mt][nt];
                st2(&dst[(size_t)s * HW + t], a[0] * SCALE, a[1] * SCALE);
                st2(&dst[(size_t)(s + 8) * HW + t], a[2] * SCALE, a[3] * SCALE);
            }
        }
    }
    if (MODE == 2) {
#pragma unroll
        for (int mt = 0; mt < 2; mt++) {
            const int s = bm + wm + mt * 16 + gid;
#pragma unroll
            for (int nt = 0; nt < 2 * NP; nt++) {
                const int c = bn + wn + nt * 8 + qid;
                float* a = acc[mt][nt];
                const size_t i0 = ((size_t)bz * HW + s) * CH + c;
                const size_t i1 = ((size_t)bz * HW + s + 8) * CH + c;
                split_st(g_aoh, g_aol, i0, a[0], a[1]);
                split_st(g_aoh, g_aol, i1, a[2], a[3]);
            }
        }
    }
    if (MODE == 3) {
#pragma unroll
        for (int mt = 0; mt < 2; mt++) {
            const int o = bm + wm + mt * 16 + gid;
            const float bo0 = bias[o], bo8 = bias[o + 8];
#pragma unroll
            for (int nt = 0; nt < 2 * NP; nt++) {
                const int s = bn + wn + nt * 8 + qid;
                float* a = acc[mt][nt];
                size_t i0 = ((size_t)bz * CH + o) * HW + s;
                size_t i1 = ((size_t)bz * CH + o + 8) * HW + s;
                float2 rv0 = *(const float2*)&resid[i0];
                float2 rv1 = *(const float2*)&resid[i1];
                st2(&Cout[i0], a[0] + bo0 + rv0.x, a[1] + bo0 + rv0.y);
                st2(&Cout[i1], a[2] + bo8 + rv1.x, a[3] + bo8 + rv1.y);
            }
        }
    }
}

// ---------------- weight conversion ------------------------------------------
__global__ void convert_w(const float* __restrict__ wqkv, const float* __restrict__ wout)
{
    const int i = blockIdx.x * 256 + threadIdx.x;
    if (i < 3 * CH * CH) {
        float v = wqkv[i];
        __half h = __float2half_rn(v);
        g_wqh[i] = h;
        g_wql[i] = __float2half_rn(v - __half2float(h));
    }
    if (i < CH * CH)
        g_woh[i] = __float2half_rn(wout[i]);
}

// ---------------- GroupNorm (smem-cached x; writes x_norm^T fp16) -------------
__global__ void gn_kernel(const float* __restrict__ x,
                          const float* __restrict__ wt,
                          const float* __restrict__ bs)
{
    extern __shared__ __half xc[];          // 32*1024 halfs = 64KB
    const int bg = blockIdx.x;              // b*8+g
    const int b = bg >> 3, g = bg & 7;
    const size_t base = (size_t)bg * (32 * HW);
    const int t = threadIdx.x;
    const float4* x4 = (const float4*)(x + base);

    float s = 0.f, s2 = 0.f;
#pragma unroll 4
    for (int i = t; i < 32 * HW / 4; i += 256) {
        float4 v = x4[i];
        s += v.x + v.y + v.z + v.w;
        s2 += v.x * v.x + v.y * v.y + v.z * v.z + v.w * v.w;
        __half2 h01 = __floats2half2_rn(v.x, v.y);
        __half2 h23 = __floats2half2_rn(v.z, v.w);
        uint2 pk; pk.x = *(uint32_t*)&h01; pk.y = *(uint32_t*)&h23;
        *(uint2*)(xc + i * 4) = pk;
    }
    __shared__ float rs[256], rq[256];
    rs[t] = s; rq[t] = s2;
    __syncthreads();
    for (int o = 128; o > 0; o >>= 1) {
        if (t < o) { rs[t] += rs[t + o]; rq[t] += rq[t + o]; }
        __syncthreads();
    }
    __shared__ float s_m, s_r;
    if (t == 0) {
        float m = rs[0] * (1.0f / (32.f * HW));
        float v = rq[0] * (1.0f / (32.f * HW)) - m * m;
        s_m = m; s_r = rsqrtf(v + EPSV);
    }
    __syncthreads();
    __shared__ float cw[32], cb[32];
    if (t < 32) {
        float w = wt[g * 32 + t] * s_r;
        cw[t] = w;
        cb[t] = bs[g * 32 + t] - s_m * w;
    }
    __syncthreads();

    __shared__ float sm[32][33];
    const int row = t >> 5, col = t & 31;
    for (int s0 = 0; s0 < HW; s0 += 32) {
#pragma unroll
        for (int cr = 0; cr < 32; cr += 8) {
            int c = cr + row;
            sm[c][col] = __half2float(xc[c * HW + s0 + col]) * cw[c] + cb[c];
        }
        __syncthreads();
#pragma unroll
        for (int sr = 0; sr < 32; sr += 8) {
            int sl = sr + row;
            g_hxnt[((size_t)b * HW + s0 + sl) * CH + g * 32 + col] =
                __float2half_rn(sm[col][sl]);
        }
        __syncthreads();
    }
}

// ---------------- softmax (fp32 scores -> fp16 probs) -------------------------
__global__ void softmax_kernel()
{
    const float* row = g_attn + (size_t)blockIdx.x * HW;
    __half* orow = g_ph + (size_t)blockIdx.x * HW;
    const int t = threadIdx.x;
    float4 v = ((const float4*)row)[t];

    float m = fmaxf(fmaxf(v.x, v.y), fmaxf(v.z, v.w));
#pragma unroll
    for (int o = 16; o > 0; o >>= 1) m = fmaxf(m, __shfl_xor_sync(0xffffffffu, m, o));
    __shared__ float red[8];
    if ((t & 31) == 0) red[t >> 5] = m;
    __syncthreads();
    float mm = red[0];
#pragma unroll
    for (int i = 1; i < 8; i++) mm = fmaxf(mm, red[i]);
    __syncthreads();

    float e0 = __expf(v.x - mm), e1 = __expf(v.y - mm);
    float e2 = __expf(v.z - mm), e3 = __expf(v.w - mm);
    float s = e0 + e1 + e2 + e3;
#pragma unroll
    for (int o = 16; o > 0; o >>= 1) s += __shfl_xor_sync(0xffffffffu, s, o);
    if ((t & 31) == 0) red[t >> 5] = s;
    __syncthreads();
    float tot = 0.f;
#pragma unroll
    for (int i = 0; i < 8; i++) tot += red[i];
    float inv = 1.0f / tot;

    uint2 pk;
    __half2 p01 = __floats2half2_rn(e0 * inv, e1 * inv);
    __half2 p23 = __floats2half2_rn(e2 * inv, e3 * inv);
    pk.x = *(uint32_t*)&p01; pk.y = *(uint32_t*)&p23;
    *(uint2*)(orow + t * 4) = pk;
}

// ---------------- launch -------------------------------------------------------
extern "C" void kernel_launch(void* const* d_in, const int* in_sizes, int n_in,
                              void* d_out, int out_size)
{
    const float* x    = (const float*)d_in[0];
    const float* gnw  = (const float*)d_in[1];
    const float* gnb  = (const float*)d_in[2];
    const float* wqkv = (const float*)d_in[3];
    const float* bqkv = (const float*)d_in[4];
    const float* wout = (const float*)d_in[5];
    const float* bout = (const float*)d_in[6];
    float* out = (float*)d_out;

    // split NT=64: 3*(9216 + 2*4608)*2 = 110592 ; plain NT=128: 3*(9216+9216)*2 = 110592
    const uint32_t smem_gemm = 110592;
    const uint32_t smem_gn   = 65536;

    cudaFuncSetAttribute(mma_gemm<0,1,64>,  cudaFuncAttributeMaxDynamicSharedMemorySize, smem_gemm);
    cudaFuncSetAttribute(mma_gemm<1,0,128>, cudaFuncAttributeMaxDynamicSharedMemorySize, smem_gemm);
    cudaFuncSetAttribute(mma_gemm<2,0,128>, cudaFuncAttributeMaxDynamicSharedMemorySize, smem_gemm);
    cudaFuncSetAttribute(mma_gemm<3,1,64>,  cudaFuncAttributeMaxDynamicSharedMemorySize, smem_gemm);
    cudaFuncSetAttribute(gn_kernel, cudaFuncAttributeMaxDynamicSharedMemorySize, smem_gn);

    convert_w<<<(3 * CH * CH + 255) / 256, 256>>>(wqkv, wout);
    gn_kernel<<<BATCH * 8, 256, smem_gn>>>(x, gnw, gnb);
    mma_gemm<0,1,64><<<dim3(12, 8, BATCH), 256, smem_gemm>>>(bqkv, nullptr, nullptr);
    mma_gemm<1,0,128><<<dim3(8, 8, BATCH), 256, smem_gemm>>>(nullptr, nullptr, nullptr);
    softmax_kernel<<<BATCH * HW, 256>>>();
    mma_gemm<2,0,128><<<dim3(2, 8, BATCH), 256, smem_gemm>>>(nullptr, nullptr, nullptr);
    mma_gemm<3,1,64><<<dim3(16, 2, BATCH), 256, smem_gemm>>>(bout, x, out);
}

// round 11
// speedup vs baseline: 6.4319x; 1.0784x over previous
#include <cuda_runtime.h>
#include <cuda_fp16.h>
#include <cstdint>

#define BATCH 32
#define CH    256
#define HW    1024
#define EPSV  1e-5f
#define SCALE 0.0625f

// ---------------- scratch (device globals; no allocation allowed) ----------
__device__ __align__(256) __half  g_hxnt[(size_t)BATCH * HW * CH];  // [b][s][c]
__device__ __align__(256) __half  g_qh  [(size_t)BATCH * HW * CH];  // [b][s][c]
__device__ __align__(256) __half  g_kh  [(size_t)BATCH * HW * CH];  // [b][t][c]
__device__ __align__(256) __half  g_vh  [(size_t)BATCH * CH * HW];  // [b][c][t]
__device__ __align__(256) __half  g_attn[(size_t)BATCH * HW * HW];  // fp16 scores
__device__ __align__(256) __half  g_ph  [(size_t)BATCH * HW * HW];  // fp16 probs
__device__ __align__(256) __half  g_aoh [(size_t)BATCH * HW * CH];  // [b][s][c]
__device__ __align__(256) __half  g_aol [(size_t)BATCH * HW * CH];
__device__ __align__(256) __half  g_wqh [3 * CH * CH];
__device__ __align__(256) __half  g_woh [CH * CH];

// ---------------- helpers ----------------------------------------------------
__device__ __forceinline__ uint32_t smem_u32(const void* p) {
    uint32_t a;
    asm("{ .reg .u64 t; cvta.to.shared.u64 t, %1; cvt.u32.u64 %0, t; }" : "=r"(a) : "l"(p));
    return a;
}

__device__ __forceinline__ void ldsm4(uint32_t* r, uint32_t addr) {
    asm volatile("ldmatrix.sync.aligned.m8n8.x4.shared.b16 {%0,%1,%2,%3}, [%4];"
        : "=r"(r[0]), "=r"(r[1]), "=r"(r[2]), "=r"(r[3]) : "r"(addr));
}

__device__ __forceinline__ void mma16816(float* c, const uint32_t* a, uint32_t b0, uint32_t b1) {
    asm volatile("mma.sync.aligned.m16n8k16.row.col.f32.f16.f16.f32 "
        "{%0,%1,%2,%3}, {%4,%5,%6,%7}, {%8,%9}, {%0,%1,%2,%3};"
        : "+f"(c[0]), "+f"(c[1]), "+f"(c[2]), "+f"(c[3])
        : "r"(a[0]), "r"(a[1]), "r"(a[2]), "r"(a[3]), "r"(b0), "r"(b1));
}

#define CP16(dst, src) \
    asm volatile("cp.async.cg.shared.global [%0], [%1], 16;" :: "r"(dst), "l"(src))
#define CPCOMMIT() asm volatile("cp.async.commit_group;" ::: "memory")
#define CPWAIT1()  asm volatile("cp.async.wait_group 1;"  ::: "memory")

__device__ __forceinline__ void st2(float* p, float x, float y) {
    float2 v; v.x = x; v.y = y; *(float2*)p = v;
}
__device__ __forceinline__ void sth2(__half* p, float x, float y) {
    *(__half2*)p = __floats2half2_rn(x, y);
}
__device__ __forceinline__ void split_st(__half* hp, __half* lp, size_t i, float x, float y) {
    __half2 h = __floats2half2_rn(x, y);
    float lx = x - __half2float(h.x), ly = y - __half2float(h.y);
    *(__half2*)(hp + i) = h;
    *(__half2*)(lp + i) = __floats2half2_rn(lx, ly);
}

// ---------------- unified HMMA GEMM (128xNT tile, K-chunk 64, 3-stage) -------
// D[m][n] = sum_k A[m][k]*B[n][k]. A plain fp16; B split hi/lo iff SPLITB.
// MODE 0 (SPLITB=0,NT=64) : A=hxnt[s][c], B=wq      -> q_h/k_h/v_h(transposed) + bias
// MODE 1 (SPLITB=0,NT=128): A=q_h[s][c],  B=k_h[t][c]-> attn[s][t]*SCALE (fp16)
// MODE 2 (SPLITB=0,NT=128): A=p_h[s][t],  B=v_h[c][t]-> ao h/l [s][c]
// MODE 3 (SPLITB=1,NT=64) : A=woh[o][c],  B=ao h/l   -> out[o][s] + bias + resid
#define KC     64                  // K per chunk
#define LDS    72                  // padded fp16 row stride (144B)
#define AELEM  (128 * LDS)         // 9216 halfs
#define OFF_BH (AELEM * 2)         // 18432 B

template <int KTOT, int SPLITB, int NT>
__device__ __forceinline__ void stage_chunk(
    const __half* __restrict__ Ap, const __half* __restrict__ Bph,
    const __half* __restrict__ Bpl, uint32_t sbuf, int tid, int k0)
{
#pragma unroll
    for (int s = 0; s < 4; s++) {                       // A: 128 rows x 8 segs
        const int slot = tid + s * 256;
        const int row = slot >> 3, seg = slot & 7;
        CP16(sbuf + (uint32_t)((row * LDS + seg * 8) * 2),
             Ap + (size_t)row * KTOT + k0 + seg * 8);
    }
#pragma unroll
    for (int s = 0; s < NT / 32; s++) {                 // B: NT rows x 8 segs
        const int slot = tid + s * 256;
        const int row = slot >> 3, seg = slot & 7;
        const uint32_t d = (uint32_t)((row * LDS + seg * 8) * 2);
        const size_t  g = (size_t)row * KTOT + k0 + seg * 8;
        CP16(sbuf + OFF_BH + d, Bph + g);
        if (SPLITB)
            CP16(sbuf + OFF_BH + (uint32_t)(NT * LDS * 2) + d, Bpl + g);
    }
}

template <int MODE, int SPLITB, int NT>
__global__ void __launch_bounds__(256, 2) mma_gemm(
    const float* __restrict__ bias,
    const float* __restrict__ resid, float* __restrict__ Cout)
{
    constexpr int KTOT = (MODE == 2) ? 1024 : 256;
    constexpr int NCH = KTOT / KC;
    constexpr int NP = NT / 32;                          // B ldsm tiles per ks
    constexpr uint32_t STAGEB = (AELEM + (SPLITB ? 2 : 1) * NT * LDS) * 2;
    extern __shared__ __half dsm[];

    const int tid = threadIdx.x;
    const int lane = tid & 31, wid = tid >> 5;
    const int bz = blockIdx.z;
    const int bm = blockIdx.y * 128, bn = blockIdx.x * NT;

    const __half *Ah, *Bh, *Bl = nullptr;
    if (MODE == 0) { Ah = g_hxnt + (size_t)bz * HW * CH; Bh = g_wqh; }
    if (MODE == 1) { Ah = g_qh + (size_t)bz * HW * CH;   Bh = g_kh + (size_t)bz * HW * CH; }
    if (MODE == 2) { Ah = g_ph + (size_t)bz * HW * HW;   Bh = g_vh + (size_t)bz * CH * HW; }
    if (MODE == 3) { Ah = g_woh; Bh = g_aoh + (size_t)bz * HW * CH; Bl = g_aol + (size_t)bz * HW * CH; }

    const __half* Ap  = Ah + (size_t)bm * KTOT;
    const __half* Bph = Bh + (size_t)bn * KTOT;
    const __half* Bpl = SPLITB ? (Bl + (size_t)bn * KTOT) : nullptr;

    const int wm = (wid >> 1) * 32, wn = (wid & 1) * (NT / 2);

    // ldmatrix base addresses relative to stage 0
    const uint32_t u0 = smem_u32(dsm);
    const int rowA = wm + (lane & 15);
    const int kOffA = (lane >> 4) << 3;
    const int rowB = wn + (lane & 7) + ((lane >> 4) << 3);
    const int kOffB = ((lane >> 3) & 1) << 3;
    uint32_t aHb[2], bHb[NP];
#pragma unroll
    for (int mt = 0; mt < 2; mt++)
        aHb[mt] = u0 + (uint32_t)(((rowA + mt * 16) * LDS + kOffA) * 2);
#pragma unroll
    for (int p = 0; p < NP; p++)
        bHb[p] = u0 + (uint32_t)OFF_BH + (uint32_t)(((rowB + p * 16) * LDS + kOffB) * 2);

    float acc[2][2 * NP][4] = {};

    // prologue: issue chunks 0 and 1
    stage_chunk<KTOT, SPLITB, NT>(Ap, Bph, Bpl, u0, tid, 0);
    CPCOMMIT();
    stage_chunk<KTOT, SPLITB, NT>(Ap, Bph, Bpl, u0 + STAGEB, tid, KC);
    CPCOMMIT();

    for (int ch = 0; ch < NCH; ch++) {
        CPWAIT1();                 // chunk ch resident
        __syncthreads();
        if (ch + 2 < NCH) {
            const int nb = (ch + 2) % 3;
            stage_chunk<KTOT, SPLITB, NT>(Ap, Bph, Bpl, u0 + nb * STAGEB, tid, (ch + 2) * KC);
        }
        CPCOMMIT();                // uniform commit count

        const uint32_t boff = (uint32_t)((ch % 3) * STAGEB);
#pragma unroll
        for (int ks = 0; ks < 4; ks++) {
            uint32_t ahf[2][4];
#pragma unroll
            for (int mt = 0; mt < 2; mt++)
                ldsm4(ahf[mt], aHb[mt] + boff + ks * 32);
#pragma unroll
            for (int p = 0; p < NP; p++) {
                uint32_t bhf[4];
                ldsm4(bhf, bHb[p] + boff + ks * 32);
#pragma unroll
                for (int mt = 0; mt < 2; mt++)
#pragma unroll
                    for (int h = 0; h < 2; h++)
                        mma16816(acc[mt][p * 2 + h], ahf[mt], bhf[h * 2], bhf[h * 2 + 1]);
                if (SPLITB) {
                    uint32_t blf[4];
                    ldsm4(blf, bHb[p] + boff + (uint32_t)(NT * LDS * 2) + ks * 32);
#pragma unroll
                    for (int mt = 0; mt < 2; mt++)
#pragma unroll
                        for (int h = 0; h < 2; h++)
                            mma16816(acc[mt][p * 2 + h], ahf[mt], blf[h * 2], blf[h * 2 + 1]);
                }
            }
        }
    }

    // ---------------- epilogue -----------------------------------------------
    const int gid = lane >> 2, qid = (lane & 3) * 2;

    if (MODE == 0) {
#pragma unroll
        for (int mt = 0; mt < 2; mt++) {
            const int s = bm + wm + mt * 16 + gid;
#pragma unroll
            for (int nt = 0; nt < 2 * NP; nt++) {
                const int oc = bn + wn + nt * 8 + qid;      // 0..767
                const int third = oc >> 8;
                const int cl = oc & 255;
                const float b0v = bias[oc], b1v = bias[oc + 1];
                float* a = acc[mt][nt];
                const float v0 = a[0] + b0v, v1 = a[1] + b1v;
                const float v2 = a[2] + b0v, v3 = a[3] + b1v;
                if (third == 0) {
                    const size_t i0 = ((size_t)bz * HW + s) * CH + cl;
                    const size_t i1 = ((size_t)bz * HW + s + 8) * CH + cl;
                    sth2(&g_qh[i0], v0, v1);
                    sth2(&g_qh[i1], v2, v3);
                } else if (third == 1) {
                    const size_t i0 = ((size_t)bz * HW + s) * CH + cl;
                    const size_t i1 = ((size_t)bz * HW + s + 8) * CH + cl;
                    sth2(&g_kh[i0], v0, v1);
                    sth2(&g_kh[i1], v2, v3);
                } else {
                    __half* vb = g_vh + (size_t)bz * CH * HW;
                    vb[(size_t)cl * HW + s]           = __float2half_rn(v0);
                    vb[(size_t)(cl + 1) * HW + s]     = __float2half_rn(v1);
                    vb[(size_t)cl * HW + s + 8]       = __float2half_rn(v2);
                    vb[(size_t)(cl + 1) * HW + s + 8] = __float2half_rn(v3);
                }
            }
        }
    }
    if (MODE == 1) {
        __half* dst = g_attn + (size_t)bz * HW * HW;
#pragma unroll
        for (int mt = 0; mt < 2; mt++) {
            const int s = bm + wm + mt * 16 + gid;
#pragma unroll
            for (int nt = 0; nt < 2 * NP; nt++) {
                const int t = bn + wn + nt * 8 + qid;
                float* a = acc[mt][nt];
                sth2(&dst[(size_t)s * HW + t], a[0] * SCALE, a[1] * SCALE);
                sth2(&dst[(size_t)(s + 8) * HW + t], a[2] * SCALE, a[3] * SCALE);
            }
        }
    }
    if (MODE == 2) {
#pragma unroll
        for (int mt = 0; mt < 2; mt++) {
            const int s = bm + wm + mt * 16 + gid;
#pragma unroll
            for (int nt = 0; nt < 2 * NP; nt++) {
                const int c = bn + wn + nt * 8 + qid;
                float* a = acc[mt][nt];
                const size_t i0 = ((size_t)bz * HW + s) * CH + c;
                const size_t i1 = ((size_t)bz * HW + s + 8) * CH + c;
                split_st(g_aoh, g_aol, i0, a[0], a[1]);
                split_st(g_aoh, g_aol, i1, a[2], a[3]);
            }
        }
    }
    if (MODE == 3) {
#pragma unroll
        for (int mt = 0; mt < 2; mt++) {
            const int o = bm + wm + mt * 16 + gid;
            const float bo0 = bias[o], bo8 = bias[o + 8];
#pragma unroll
            for (int nt = 0; nt < 2 * NP; nt++) {
                const int s = bn + wn + nt * 8 + qid;
                float* a = acc[mt][nt];
                size_t i0 = ((size_t)bz * CH + o) * HW + s;
                size_t i1 = ((size_t)bz * CH + o + 8) * HW + s;
                float2 rv0 = *(const float2*)&resid[i0];
                float2 rv1 = *(const float2*)&resid[i1];
                st2(&Cout[i0], a[0] + bo0 + rv0.x, a[1] + bo0 + rv0.y);
                st2(&Cout[i1], a[2] + bo8 + rv1.x, a[3] + bo8 + rv1.y);
            }
        }
    }
}

// ---------------- weight conversion ------------------------------------------
__global__ void convert_w(const float* __restrict__ wqkv, const float* __restrict__ wout)
{
    const int i = blockIdx.x * 256 + threadIdx.x;
    if (i < 3 * CH * CH)
        g_wqh[i] = __float2half_rn(wqkv[i]);
    if (i < CH * CH)
        g_woh[i] = __float2half_rn(wout[i]);
}

// ---------------- GroupNorm (smem-cached x; writes x_norm^T fp16) -------------
__global__ void gn_kernel(const float* __restrict__ x,
                          const float* __restrict__ wt,
                          const float* __restrict__ bs)
{
    extern __shared__ __half xc[];          // 32*1024 halfs = 64KB
    const int bg = blockIdx.x;              // b*8+g
    const int b = bg >> 3, g = bg & 7;
    const size_t base = (size_t)bg * (32 * HW);
    const int t = threadIdx.x;
    const float4* x4 = (const float4*)(x + base);

    float s = 0.f, s2 = 0.f;
#pragma unroll 4
    for (int i = t; i < 32 * HW / 4; i += 256) {
        float4 v = x4[i];
        s += v.x + v.y + v.z + v.w;
        s2 += v.x * v.x + v.y * v.y + v.z * v.z + v.w * v.w;
        __half2 h01 = __floats2half2_rn(v.x, v.y);
        __half2 h23 = __floats2half2_rn(v.z, v.w);
        uint2 pk; pk.x = *(uint32_t*)&h01; pk.y = *(uint32_t*)&h23;
        *(uint2*)(xc + i * 4) = pk;
    }
    __shared__ float rs[256], rq[256];
    rs[t] = s; rq[t] = s2;
    __syncthreads();
    for (int o = 128; o > 0; o >>= 1) {
        if (t < o) { rs[t] += rs[t + o]; rq[t] += rq[t + o]; }
        __syncthreads();
    }
    __shared__ float s_m, s_r;
    if (t == 0) {
        float m = rs[0] * (1.0f / (32.f * HW));
        float v = rq[0] * (1.0f / (32.f * HW)) - m * m;
        s_m = m; s_r = rsqrtf(v + EPSV);
    }
    __syncthreads();
    __shared__ float cw[32], cb[32];
    if (t < 32) {
        float w = wt[g * 32 + t] * s_r;
        cw[t] = w;
        cb[t] = bs[g * 32 + t] - s_m * w;
    }
    __syncthreads();

    __shared__ float sm[32][33];
    const int row = t >> 5, col = t & 31;
    for (int s0 = 0; s0 < HW; s0 += 32) {
#pragma unroll
        for (int cr = 0; cr < 32; cr += 8) {
            int c = cr + row;
            sm[c][col] = __half2float(xc[c * HW + s0 + col]) * cw[c] + cb[c];
        }
        __syncthreads();
#pragma unroll
        for (int sr = 0; sr < 32; sr += 8) {
            int sl = sr + row;
            g_hxnt[((size_t)b * HW + s0 + sl) * CH + g * 32 + col] =
                __float2half_rn(sm[col][sl]);
        }
        __syncthreads();
    }
}

// ---------------- softmax (fp16 scores -> fp16 probs) -------------------------
__global__ void softmax_kernel()
{
    const __half* row = g_attn + (size_t)blockIdx.x * HW;
    __half* orow = g_ph + (size_t)blockIdx.x * HW;
    const int t = threadIdx.x;
    uint2 raw = *(const uint2*)(row + t * 4);
    __half2 h01 = *(__half2*)&raw.x;
    __half2 h23 = *(__half2*)&raw.y;
    float vx = __half2float(h01.x), vy = __half2float(h01.y);
    float vz = __half2float(h23.x), vw = __half2float(h23.y);

    float m = fmaxf(fmaxf(vx, vy), fmaxf(vz, vw));
#pragma unroll
    for (int o = 16; o > 0; o >>= 1) m = fmaxf(m, __shfl_xor_sync(0xffffffffu, m, o));
    __shared__ float red[8];
    if ((t & 31) == 0) red[t >> 5] = m;
    __syncthreads();
    float mm = red[0];
#pragma unroll
    for (int i = 1; i < 8; i++) mm = fmaxf(mm, red[i]);
    __syncthreads();

    float e0 = __expf(vx - mm), e1 = __expf(vy - mm);
    float e2 = __expf(vz - mm), e3 = __expf(vw - mm);
    float s = e0 + e1 + e2 + e3;
#pragma unroll
    for (int o = 16; o > 0; o >>= 1) s += __shfl_xor_sync(0xffffffffu, s, o);
    if ((t & 31) == 0) red[t >> 5] = s;
    __syncthreads();
    float tot = 0.f;
#pragma unroll
    for (int i = 0; i < 8; i++) tot += red[i];
    float inv = 1.0f / tot;

    uint2 pk;
    __half2 p01 = __floats2half2_rn(e0 * inv, e1 * inv);
    __half2 p23 = __floats2half2_rn(e2 * inv, e3 * inv);
    pk.x = *(uint32_t*)&p01; pk.y = *(uint32_t*)&p23;
    *(uint2*)(orow + t * 4) = pk;
}

// ---------------- launch -------------------------------------------------------
extern "C" void kernel_launch(void* const* d_in, const int* in_sizes, int n_in,
                              void* d_out, int out_size)
{
    const float* x    = (const float*)d_in[0];
    const float* gnw  = (const float*)d_in[1];
    const float* gnb  = (const float*)d_in[2];
    const float* wqkv = (const float*)d_in[3];
    const float* bqkv = (const float*)d_in[4];
    const float* wout = (const float*)d_in[5];
    const float* bout = (const float*)d_in[6];
    float* out = (float*)d_out;

    // plain NT=64: 3*(9216+4608)*2 = 82944 ; plain NT=128: 110592 ; split NT=64: 110592
    const uint32_t smem_m0 = 82944;
    const uint32_t smem_big = 110592;
    const uint32_t smem_gn = 65536;

    cudaFuncSetAttribute(mma_gemm<0,0,64>,  cudaFuncAttributeMaxDynamicSharedMemorySize, smem_m0);
    cudaFuncSetAttribute(mma_gemm<1,0,128>, cudaFuncAttributeMaxDynamicSharedMemorySize, smem_big);
    cudaFuncSetAttribute(mma_gemm<2,0,128>, cudaFuncAttributeMaxDynamicSharedMemorySize, smem_big);
    cudaFuncSetAttribute(mma_gemm<3,1,64>,  cudaFuncAttributeMaxDynamicSharedMemorySize, smem_big);
    cudaFuncSetAttribute(gn_kernel, cudaFuncAttributeMaxDynamicSharedMemorySize, smem_gn);

    convert_w<<<(3 * CH * CH + 255) / 256, 256>>>(wqkv, wout);
    gn_kernel<<<BATCH * 8, 256, smem_gn>>>(x, gnw, gnb);
    mma_gemm<0,0,64><<<dim3(12, 8, BATCH), 256, smem_m0>>>(bqkv, nullptr, nullptr);
    mma_gemm<1,0,128><<<dim3(8, 8, BATCH), 256, smem_big>>>(nullptr, nullptr, nullptr);
    softmax_kernel<<<BATCH * HW, 256>>>();
    mma_gemm<2,0,128><<<dim3(2, 8, BATCH), 256, smem_big>>>(nullptr, nullptr, nullptr);
    mma_gemm<3,1,64><<<dim3(16, 2, BATCH), 256, smem_big>>>(bout, x, out);
}